// round 11
// baseline (speedup 1.0000x reference)
#include <cuda_runtime.h>
#include <cuda_bf16.h>
#include <cstdint>
#include <math.h>

#define B_  8
#define L_  4096
#define D_  1024
#define M_  64
#define BL_ (B_*L_)
#define C_  64
#define T_  64

typedef unsigned long long u64;
typedef unsigned int u32;
typedef unsigned short u16;

// ---------------- scratch (split-bf16 canonical intermediates) -------------
__device__ u32   g_QH[BL_*32], g_QL[BL_*32];   // Q  split pairs [row][pair]
__device__ u32   g_KH[BL_*32], g_KL[BL_*32];   // gated K
__device__ u32   g_VH[BL_*32], g_VL[BL_*32];   // gated V
__device__ u32   g_OH[BL_*32], g_OL[BL_*32];   // pre-Wo output O
__device__ float g_A   [B_*C_*M_*M_];          // chunk summaries (TRANSPOSED: A^T[j][i])
__device__ float g_Spre[B_*C_*M_*M_];          // Spre^T[j][m]
__device__ u16   g_Wh  [32*192*32];
__device__ u16   g_Wl  [32*192*32];
__device__ u32   g_WoH [8*128*32];
__device__ u32   g_WoL [8*128*32];

__device__ __forceinline__ float decay_val(const float* dp) {
    return 0.9f + 0.099f / (1.0f + expf(-dp[0]));
}

// ---- helpers ----
__device__ __forceinline__ u32 smem_u32(const void* p) {
    u32 a;
    asm("{ .reg .u64 t; cvta.to.shared.u64 t, %1; cvt.u32.u64 %0, t; }" : "=r"(a) : "l"(p));
    return a;
}
__device__ __forceinline__ void ldsm4(u32& r0, u32& r1, u32& r2, u32& r3, u32 a) {
    asm volatile("ldmatrix.sync.aligned.m8n8.x4.shared.b16 {%0,%1,%2,%3},[%4];"
                 : "=r"(r0), "=r"(r1), "=r"(r2), "=r"(r3) : "r"(a));
}
__device__ __forceinline__ void mma_bf16(float* d, const u32* a, const u32* b) {
    asm volatile(
        "mma.sync.aligned.m16n8k16.row.col.f32.bf16.bf16.f32 "
        "{%0,%1,%2,%3},{%4,%5,%6,%7},{%8,%9},{%0,%1,%2,%3};"
        : "+f"(d[0]), "+f"(d[1]), "+f"(d[2]), "+f"(d[3])
        : "r"(a[0]), "r"(a[1]), "r"(a[2]), "r"(a[3]), "r"(b[0]), "r"(b[1]));
}
__device__ __forceinline__ void split2(float x0, float x1, u32& hi, u32& lo) {
    __nv_bfloat162 h = __floats2bfloat162_rn(x0, x1);
    float r0 = x0 - __bfloat162float(h.x);
    float r1 = x1 - __bfloat162float(h.y);
    __nv_bfloat162 l = __floats2bfloat162_rn(r0, r1);
    hi = *(u32*)&h;  lo = *(u32*)&l;
}
__device__ __forceinline__ void split1(float x, u16& hi, u16& lo) {
    __nv_bfloat16 h = __float2bfloat16(x);
    __nv_bfloat16 l = __float2bfloat16(x - __bfloat162float(h));
    hi = *(u16*)&h;  lo = *(u16*)&l;
}
__device__ __forceinline__ float bflo(u32 v) {
    u16 h = (u16)(v & 0xffff);
    return __bfloat162float(*(__nv_bfloat16*)&h);
}
__device__ __forceinline__ float bfhi(u32 v) {
    u16 h = (u16)(v >> 16);
    return __bfloat162float(*(__nv_bfloat16*)&h);
}
__device__ __forceinline__ void cpasync16(u32 dst, const void* src) {
    asm volatile("cp.async.cg.shared.global [%0], [%1], 16;" :: "r"(dst), "l"(src));
}

// ---------- kernel 0a: W prep ----------
__global__ void wprep_kernel(const float* __restrict__ Wq,
                             const float* __restrict__ Wk,
                             const float* __restrict__ Wv) {
    int idx = blockIdx.x*256 + threadIdx.x;
    int kk = idx & 31;
    int r  = idx >> 5;
    int n  = r % 192;
    int it = r / 192;
    int col = n & 63;
    const float* Wp = (n < 64) ? Wq : (n < 128) ? Wk : Wv;
    float w = Wp[(size_t)(it*32 + kk)*M_ + col];
    u16 hi, lo;
    split1(w, hi, lo);
    g_Wh[idx] = hi;
    g_Wl[idx] = lo;
}

// ---------- kernel 0b: Wo prep ----------
__global__ void woprep_kernel(const float* __restrict__ Wo) {
    int idx = blockIdx.x*256 + threadIdx.x;
    int kp = idx & 31;
    int n  = (idx >> 5) & 127;
    int blk = idx >> 12;
    int ng = blk*128 + n;
    u32 hi, lo;
    split2(Wo[(size_t)(2*kp)*D_ + ng], Wo[(size_t)(2*kp+1)*D_ + ng], hi, lo);
    g_WoH[idx] = hi;
    g_WoL[idx] = lo;
}

// SMEM layout for qkv, double-buffered, 64-row tiles. Row stride 80 B.
#define RS 80
#define XHo(b)  ((b)*5120)
#define XLo(b)  (10240 + (b)*5120)
#define WHo(b)  (20480 + (b)*15360)
#define WLo(b)  (51200 + (b)*15360)
#define WGV_OFF 81920
#define GATE_OFF 86016
#define QKV_SMEM 86528

// ========== kernel 1: fused QKV+gate, warp MMA, 2 CTAs/SM ====
__global__ void __launch_bounds__(256, 2) qkv_mma_kernel(
        const float* __restrict__ x,
        const float* __restrict__ Wg, const float* __restrict__ bg) {
    extern __shared__ char smem[];
    u32 sb = smem_u32(smem);
    int t = threadIdx.x;
    int lane = t & 31, wid = t >> 5;
    int warp_m = wid >> 2, warp_n = wid & 3;
    int r0 = blockIdx.x * 64;

    *(float4*)(smem + WGV_OFF + t*16) = *(const float4*)(Wg + t*4);
    const float* wgs = (const float*)(smem + WGV_OFF);

    int rowX = t >> 3;
    int c4   = t & 7;

    int wn[6], wc[6], wterm[6];
#pragma unroll
    for (int rr = 0; rr < 6; ++rr) {
        int idx = t + rr*256;
        wterm[rr] = (idx >= 768);
        int rem = idx - wterm[rr]*768;
        wn[rr] = rem >> 2;
        wc[rr] = rem & 3;
    }

    int laneA_row = lane & 15;
    int laneA_kb  = (lane >> 4) * 16;
    int laneB_n   = (lane & 7) + ((lane >> 4) << 3);
    int laneB_kb  = ((lane >> 3) & 1) * 16;

    float acc[2][6][4];
#pragma unroll
    for (int i = 0; i < 2; ++i)
#pragma unroll
        for (int j = 0; j < 6; ++j)
#pragma unroll
            for (int k = 0; k < 4; ++k) acc[i][j][k] = 0.f;
    float gacc[2] = {0.f, 0.f};

    __syncthreads();

    float4 xr0 = *(const float4*)(x + (size_t)(r0 + rowX)*D_ + c4*4);
    float4 xr1 = *(const float4*)(x + (size_t)(r0 + rowX + 32)*D_ + c4*4);
#pragma unroll
    for (int rr = 0; rr < 6; ++rr) {
        u32 dst = sb + (wterm[rr] ? WLo(0) : WHo(0)) + wn[rr]*RS + wc[rr]*16;
        const u16* src = (wterm[rr] ? g_Wl : g_Wh) + ((0*192 + wn[rr])*32 + wc[rr]*8);
        cpasync16(dst, src);
    }
    asm volatile("cp.async.commit_group;" ::: "memory");

#pragma unroll 1
    for (int it = 0; it < 32; ++it) {
        int buf = it & 1;
        int k0 = it * 32;
        {
            const float* wg4 = wgs + k0 + c4*4;
            gacc[0] += xr0.x*wg4[0] + xr0.y*wg4[1] + xr0.z*wg4[2] + xr0.w*wg4[3];
            gacc[1] += xr1.x*wg4[0] + xr1.y*wg4[1] + xr1.z*wg4[2] + xr1.w*wg4[3];
            u32 h0,l0,h1,l1;
            split2(xr0.x, xr0.y, h0, l0);
            split2(xr0.z, xr0.w, h1, l1);
            int off = rowX*RS + c4*8;
            *(u32*)(smem + XHo(buf) + off)   = h0;
            *(u32*)(smem + XHo(buf) + off+4) = h1;
            *(u32*)(smem + XLo(buf) + off)   = l0;
            *(u32*)(smem + XLo(buf) + off+4) = l1;
            split2(xr1.x, xr1.y, h0, l0);
            split2(xr1.z, xr1.w, h1, l1);
            off = (rowX + 32)*RS + c4*8;
            *(u32*)(smem + XHo(buf) + off)   = h0;
            *(u32*)(smem + XHo(buf) + off+4) = h1;
            *(u32*)(smem + XLo(buf) + off)   = l0;
            *(u32*)(smem + XLo(buf) + off+4) = l1;
        }
        asm volatile("cp.async.wait_group 0;" ::: "memory");
        __syncthreads();
        if (it < 31) {
            int k1 = k0 + 32;
            xr0 = *(const float4*)(x + (size_t)(r0 + rowX)*D_ + k1 + c4*4);
            xr1 = *(const float4*)(x + (size_t)(r0 + rowX + 32)*D_ + k1 + c4*4);
#pragma unroll
            for (int rr = 0; rr < 6; ++rr) {
                u32 dst = sb + (wterm[rr] ? WLo(buf^1) : WHo(buf^1)) + wn[rr]*RS + wc[rr]*16;
                const u16* src = (wterm[rr] ? g_Wl : g_Wh)
                               + (((it+1)*192 + wn[rr])*32 + wc[rr]*8);
                cpasync16(dst, src);
            }
            asm volatile("cp.async.commit_group;" ::: "memory");
        }
#pragma unroll
        for (int ko = 0; ko < 2; ++ko) {
            int kb = ko*32;
            u32 Ah[2][4], Al[2][4], Bb[6][2];
#pragma unroll
            for (int mt = 0; mt < 2; ++mt) {
                u32 aoff = (u32)((warp_m*32 + mt*16 + laneA_row)*RS + kb + laneA_kb);
                ldsm4(Ah[mt][0], Ah[mt][1], Ah[mt][2], Ah[mt][3], sb + XHo(buf) + aoff);
                ldsm4(Al[mt][0], Al[mt][1], Al[mt][2], Al[mt][3], sb + XLo(buf) + aoff);
            }
#pragma unroll
            for (int np = 0; np < 3; ++np) {
                u32 boff = (u32)((warp_n*48 + np*16 + laneB_n)*RS + kb + laneB_kb);
                ldsm4(Bb[2*np][0], Bb[2*np][1], Bb[2*np+1][0], Bb[2*np+1][1],
                      sb + WHo(buf) + boff);
            }
#pragma unroll
            for (int mt = 0; mt < 2; ++mt)
#pragma unroll
                for (int nt = 0; nt < 6; ++nt) mma_bf16(acc[mt][nt], Ah[mt], Bb[nt]);
#pragma unroll
            for (int mt = 0; mt < 2; ++mt)
#pragma unroll
                for (int nt = 0; nt < 6; ++nt) mma_bf16(acc[mt][nt], Al[mt], Bb[nt]);
#pragma unroll
            for (int np = 0; np < 3; ++np) {
                u32 boff = (u32)((warp_n*48 + np*16 + laneB_n)*RS + kb + laneB_kb);
                ldsm4(Bb[2*np][0], Bb[2*np][1], Bb[2*np+1][0], Bb[2*np+1][1],
                      sb + WLo(buf) + boff);
            }
#pragma unroll
            for (int mt = 0; mt < 2; ++mt)
#pragma unroll
                for (int nt = 0; nt < 6; ++nt) mma_bf16(acc[mt][nt], Ah[mt], Bb[nt]);
        }
    }

#pragma unroll
    for (int off = 4; off; off >>= 1)
#pragma unroll
        for (int rep = 0; rep < 2; ++rep)
            gacc[rep] += __shfl_xor_sync(0xffffffffu, gacc[rep], off);
    if ((t & 7) == 0) {
        float bgv = bg[0];
        ((float*)(smem + GATE_OFF))[rowX]      = 1.0f/(1.0f + expf(-(gacc[0] + bgv)));
        ((float*)(smem + GATE_OFF))[rowX + 32] = 1.0f/(1.0f + expf(-(gacc[1] + bgv)));
    }
    __syncthreads();
    const float* gate = (const float*)(smem + GATE_OFF);

    // epilogue: write split-bf16 Q / gated-K / gated-V pairs
    int g8 = lane >> 2, t2 = lane & 3;
#pragma unroll
    for (int mt = 0; mt < 2; ++mt) {
        int rl0 = warp_m*32 + mt*16 + g8;
#pragma unroll
        for (int nt = 0; nt < 6; ++nt) {
            int col = warp_n*48 + nt*8 + t2*2;
            int proj = col >> 6, pair = (col & 63) >> 1;
            u32* OutH = (proj == 0) ? g_QH : (proj == 1) ? g_KH : g_VH;
            u32* OutL = (proj == 0) ? g_QL : (proj == 1) ? g_KL : g_VL;
            float ga = (proj == 0) ? 1.0f : gate[rl0];
            float gb = (proj == 0) ? 1.0f : gate[rl0 + 8];
            u32 hi, lo;
            split2(acc[mt][nt][0]*ga, acc[mt][nt][1]*ga, hi, lo);
            OutH[(size_t)(r0 + rl0)*32 + pair] = hi;
            OutL[(size_t)(r0 + rl0)*32 + pair] = lo;
            split2(acc[mt][nt][2]*gb, acc[mt][nt][3]*gb, hi, lo);
            OutH[(size_t)(r0 + rl0 + 8)*32 + pair] = hi;
            OutL[(size_t)(r0 + rl0 + 8)*32 + pair] = lo;
        }
    }
}

// ---- shared chunk constants ----
#define CRS 144

// --------- kernel 3: chunk summaries -> A^T (operands swapped) -------------
// A^T[j][i] = sum_s gv[s][j] * (d^{63-s} gk[s][i]); A-op = GV^T, B-op = GKw^T
#define CS_AH 0
#define CS_AL 9216
#define CS_BH 18432
#define CS_BL 27648
#define CS_DP 36864
#define CS_SMEM 37376

__global__ void __launch_bounds__(256) chunk_sum_kernel(const float* __restrict__ dp) {
    extern __shared__ char smem[];
    u32 sb = smem_u32(smem);
    int b = blockIdx.y, c = blockIdx.x;
    int t = threadIdx.x, lane = t & 31, wid = t >> 5;
    int warp_m = wid >> 1, warp_n = wid & 1;
    float d = decay_val(dp);
    float* dpow = (float*)(smem + CS_DP);
    if (t < 64) dpow[t] = powf(d, (float)t);
    __syncthreads();

    size_t grow = (size_t)b*L_ + (size_t)c*T_;
#pragma unroll
    for (int rep = 0; rep < 8; ++rep) {
        int idx = t + rep*256;        // 2048 = 64 s x 32 pairs
        int s = idx >> 5, p = idx & 31;
        u32 kh = g_KH[(grow+s)*32 + p], kl = g_KL[(grow+s)*32 + p];
        u32 vh = g_VH[(grow+s)*32 + p], vl = g_VL[(grow+s)*32 + p];
        float w = dpow[63 - s];
        // GV^T -> A operand (direct u16 moves)
        *(u16*)(smem + CS_AH + (2*p)*CRS   + s*2) = (u16)(vh & 0xffff);
        *(u16*)(smem + CS_AH + (2*p+1)*CRS + s*2) = (u16)(vh >> 16);
        *(u16*)(smem + CS_AL + (2*p)*CRS   + s*2) = (u16)(vl & 0xffff);
        *(u16*)(smem + CS_AL + (2*p+1)*CRS + s*2) = (u16)(vl >> 16);
        // GKw^T -> B operand (reconstruct, weight, re-split)
        float f0 = (bflo(kh) + bflo(kl)) * w;
        float f1 = (bfhi(kh) + bfhi(kl)) * w;
        u16 hi, lo;
        split1(f0, hi, lo);
        *(u16*)(smem + CS_BH + (2*p)*CRS + s*2) = hi;
        *(u16*)(smem + CS_BL + (2*p)*CRS + s*2) = lo;
        split1(f1, hi, lo);
        *(u16*)(smem + CS_BH + (2*p+1)*CRS + s*2) = hi;
        *(u16*)(smem + CS_BL + (2*p+1)*CRS + s*2) = lo;
    }
    __syncthreads();

    int laneA_row = lane & 15;
    int laneA_kb  = (lane >> 4) * 16;
    int laneB_n   = (lane & 7) + ((lane >> 4) << 3);
    int laneB_kb  = ((lane >> 3) & 1) * 16;

    float acc[4][4];
#pragma unroll
    for (int j = 0; j < 4; ++j)
#pragma unroll
        for (int k = 0; k < 4; ++k) acc[j][k] = 0.f;

#pragma unroll
    for (int ko = 0; ko < 4; ++ko) {
        int kb = ko*32;
        u32 Ah[4], Al[4], Bb[4][2];
        u32 aoff = (u32)((warp_m*16 + laneA_row)*CRS + kb + laneA_kb);
        ldsm4(Ah[0], Ah[1], Ah[2], Ah[3], sb + CS_AH + aoff);
        ldsm4(Al[0], Al[1], Al[2], Al[3], sb + CS_AL + aoff);
#pragma unroll
        for (int np = 0; np < 2; ++np) {
            u32 boff = (u32)((warp_n*32 + np*16 + laneB_n)*CRS + kb + laneB_kb);
            ldsm4(Bb[2*np][0], Bb[2*np][1], Bb[2*np+1][0], Bb[2*np+1][1],
                  sb + CS_BH + boff);
        }
#pragma unroll
        for (int nt = 0; nt < 4; ++nt) mma_bf16(acc[nt], Ah, Bb[nt]);
#pragma unroll
        for (int nt = 0; nt < 4; ++nt) mma_bf16(acc[nt], Al, Bb[nt]);
#pragma unroll
        for (int np = 0; np < 2; ++np) {
            u32 boff = (u32)((warp_n*32 + np*16 + laneB_n)*CRS + kb + laneB_kb);
            ldsm4(Bb[2*np][0], Bb[2*np][1], Bb[2*np+1][0], Bb[2*np+1][1],
                  sb + CS_BL + boff);
        }
#pragma unroll
        for (int nt = 0; nt < 4; ++nt) mma_bf16(acc[nt], Ah, Bb[nt]);
    }

    int g8 = lane >> 2, t2 = lane & 3;
    size_t ab = (size_t)(b*C_ + c) * (M_*M_);
#pragma unroll
    for (int nt = 0; nt < 4; ++nt) {
        int j = warp_n*32 + nt*8 + t2*2;   // fragment col = i index of A^T
        int i0 = warp_m*16 + g8;           // fragment row = j index of A^T
        *(float2*)(g_A + ab + (size_t)i0*M_ + j)     = make_float2(acc[nt][0], acc[nt][1]);
        *(float2*)(g_A + ab + (size_t)(i0+8)*M_ + j) = make_float2(acc[nt][2], acc[nt][3]);
    }
}

// --------- kernel 4: inter-chunk scan (transposed arrays; MLP-8) ----------
__global__ void chunk_scan_kernel(const float* __restrict__ dp,
                                  float* __restrict__ sfinal) {
    int gid = blockIdx.x * blockDim.x + threadIdx.x;
    int b = gid >> 12;
    int e = gid & 4095;                 // e = j*64 + m in transposed layout
    float d  = decay_val(dp);
    float dT = powf(d, 64.0f);
    float S = 0.f;
#pragma unroll 1
    for (int c0 = 0; c0 < C_; c0 += 8) {
        float a[8];
#pragma unroll
        for (int j = 0; j < 8; ++j)
            a[j] = g_A[((size_t)(b*C_ + c0 + j) << 12) + e];
#pragma unroll
        for (int j = 0; j < 8; ++j) {
            g_Spre[((size_t)(b*C_ + c0 + j) << 12) + e] = S;
            S = dT*S + a[j];
        }
    }
    // sfinal is natural [m][j]: transpose back on write
    sfinal[((size_t)b << 12) + (e & 63)*64 + (e >> 6)] = S;
}

// --------- kernel 5: per-chunk outputs ----------
#define CO_QH 0
#define CO_QL 9216
#define CO_PH 18432
#define CO_PL 27648
#define CO_BH 36864
#define CO_BL 46080
#define CO_DP 55296
#define CO_SMEM 55808

__global__ void __launch_bounds__(256) chunk_out_kernel(const float* __restrict__ dp) {
    extern __shared__ char smem[];
    u32 sb = smem_u32(smem);
    int b = blockIdx.y, c = blockIdx.x;
    int t = threadIdx.x, lane = t & 31, wid = t >> 5;
    int warp_m = wid >> 1, warp_n = wid & 1;
    float d = decay_val(dp);
    float* dpow = (float*)(smem + CO_DP);
    if (t < 65) dpow[t] = powf(d, (float)t);

    size_t grow = (size_t)b*L_ + (size_t)c*T_;
    size_t sbase = (size_t)(b*C_ + c) * (M_*M_);

    // ---- stage Q (A natural) + GK (B natural) via cp.async, pre-split ----
#pragma unroll
    for (int rep = 0; rep < 2; ++rep) {
        int idx = t + rep*256;           // 512 chunks: row(64) x ch(8)
        int row = idx >> 3, ch = idx & 7;
        const u32* qh = g_QH + (grow + row)*32 + ch*4;
        const u32* ql = g_QL + (grow + row)*32 + ch*4;
        const u32* kh = g_KH + (grow + row)*32 + ch*4;
        const u32* kl = g_KL + (grow + row)*32 + ch*4;
        u32 off = row*CRS + ch*16;
        cpasync16(sb + CO_QH + off, qh);
        cpasync16(sb + CO_QL + off, ql);
        cpasync16(sb + CO_BH + off, kh);
        cpasync16(sb + CO_BL + off, kl);
    }
    asm volatile("cp.async.commit_group;" ::: "memory");
    asm volatile("cp.async.wait_group 0;" ::: "memory");
    __syncthreads();

    int laneA_row = lane & 15;
    int laneA_kb  = (lane >> 4) * 16;
    int laneB_n   = (lane & 7) + ((lane >> 4) << 3);
    int laneB_kb  = ((lane >> 3) & 1) * 16;
    int g8 = lane >> 2, t2 = lane & 3;

    // phase 1: P = Q @ GK^T
    float pacc[4][4];
#pragma unroll
    for (int j = 0; j < 4; ++j)
#pragma unroll
        for (int k = 0; k < 4; ++k) pacc[j][k] = 0.f;
#pragma unroll
    for (int ko = 0; ko < 4; ++ko) {
        int kb = ko*32;
        u32 Ah[4], Al[4], Bb[4][2];
        u32 aoff = (u32)((warp_m*16 + laneA_row)*CRS + kb + laneA_kb);
        ldsm4(Ah[0], Ah[1], Ah[2], Ah[3], sb + CO_QH + aoff);
        ldsm4(Al[0], Al[1], Al[2], Al[3], sb + CO_QL + aoff);
#pragma unroll
        for (int np = 0; np < 2; ++np) {
            u32 boff = (u32)((warp_n*32 + np*16 + laneB_n)*CRS + kb + laneB_kb);
            ldsm4(Bb[2*np][0], Bb[2*np][1], Bb[2*np+1][0], Bb[2*np+1][1],
                  sb + CO_BH + boff);
        }
#pragma unroll
        for (int nt = 0; nt < 4; ++nt) mma_bf16(pacc[nt], Ah, Bb[nt]);
#pragma unroll
        for (int nt = 0; nt < 4; ++nt) mma_bf16(pacc[nt], Al, Bb[nt]);
#pragma unroll
        for (int np = 0; np < 2; ++np) {
            u32 boff = (u32)((warp_n*32 + np*16 + laneB_n)*CRS + kb + laneB_kb);
            ldsm4(Bb[2*np][0], Bb[2*np][1], Bb[2*np+1][0], Bb[2*np+1][1],
                  sb + CO_BL + boff);
        }
#pragma unroll
        for (int nt = 0; nt < 4; ++nt) mma_bf16(pacc[nt], Ah, Bb[nt]);
    }
#pragma unroll
    for (int nt = 0; nt < 4; ++nt) {
        int colb = warp_n*32 + nt*8 + t2*2;
        int ra = warp_m*16 + g8;
        float p0 = (colb   <= ra) ? pacc[nt][0]*dpow[ra - colb]     : 0.f;
        float p1 = (colb+1 <= ra) ? pacc[nt][1]*dpow[ra - colb - 1] : 0.f;
        int rb = ra + 8;
        float p2 = (colb   <= rb) ? pacc[nt][2]*dpow[rb - colb]     : 0.f;
        float p3 = (colb+1 <= rb) ? pacc[nt][3]*dpow[rb - colb - 1] : 0.f;
        u32 hi, lo;
        split2(p0, p1, hi, lo);
        *(u32*)(smem + CO_PH + ra*CRS + colb*2) = hi;
        *(u32*)(smem + CO_PL + ra*CRS + colb*2) = lo;
        split2(p2, p3, hi, lo);
        *(u32*)(smem + CO_PH + rb*CRS + colb*2) = hi;
        *(u32*)(smem + CO_PL + rb*CRS + colb*2) = lo;
    }
    __syncthreads();

    // ---- stage Spre^T (now natural [j][m] fp32): contiguous split ----
#pragma unroll
    for (int rep = 0; rep < 4; ++rep) {
        int idx = t + rep*256;
        int row = idx >> 4, c4 = idx & 15;
        float4 v = *(const float4*)(g_Spre + sbase + (size_t)row*M_ + c4*4);
        u32 h0,l0,h1,l1;
        split2(v.x, v.y, h0, l0);
        split2(v.z, v.w, h1, l1);
        int off = row*CRS + c4*8;
        *(u32*)(smem + CO_BH + off)   = h0;
        *(u32*)(smem + CO_BH + off+4) = h1;
        *(u32*)(smem + CO_BL + off)   = l0;
        *(u32*)(smem + CO_BL + off+4) = l1;
    }
    __syncthreads();

    // phase 2: acc = Q @ Spre   (B = Spre^T natural)
    float acc[4][4];
#pragma unroll
    for (int j = 0; j < 4; ++j)
#pragma unroll
        for (int k = 0; k < 4; ++k) acc[j][k] = 0.f;
#pragma unroll
    for (int ko = 0; ko < 4; ++ko) {
        int kb = ko*32;
        u32 Ah[4], Al[4], Bb[4][2];
        u32 aoff = (u32)((warp_m*16 + laneA_row)*CRS + kb + laneA_kb);
        ldsm4(Ah[0], Ah[1], Ah[2], Ah[3], sb + CO_QH + aoff);
        ldsm4(Al[0], Al[1], Al[2], Al[3], sb + CO_QL + aoff);
#pragma unroll
        for (int np = 0; np < 2; ++np) {
            u32 boff = (u32)((warp_n*32 + np*16 + laneB_n)*CRS + kb + laneB_kb);
            ldsm4(Bb[2*np][0], Bb[2*np][1], Bb[2*np+1][0], Bb[2*np+1][1],
                  sb + CO_BH + boff);
        }
#pragma unroll
        for (int nt = 0; nt < 4; ++nt) mma_bf16(acc[nt], Ah, Bb[nt]);
#pragma unroll
        for (int nt = 0; nt < 4; ++nt) mma_bf16(acc[nt], Al, Bb[nt]);
#pragma unroll
        for (int np = 0; np < 2; ++np) {
            u32 boff = (u32)((warp_n*32 + np*16 + laneB_n)*CRS + kb + laneB_kb);
            ldsm4(Bb[2*np][0], Bb[2*np][1], Bb[2*np+1][0], Bb[2*np+1][1],
                  sb + CO_BL + boff);
        }
#pragma unroll
        for (int nt = 0; nt < 4; ++nt) mma_bf16(acc[nt], Ah, Bb[nt]);
    }
    {
        int ra = warp_m*16 + g8;
        float sa = dpow[ra + 1], sbc = dpow[ra + 9];
#pragma unroll
        for (int nt = 0; nt < 4; ++nt) {
            acc[nt][0] *= sa;  acc[nt][1] *= sa;
            acc[nt][2] *= sbc; acc[nt][3] *= sbc;
        }
    }
    __syncthreads();

    // ---- stage GV^T from pre-split pairs ----
#pragma unroll
    for (int rep = 0; rep < 8; ++rep) {
        int idx = t + rep*256;
        int s = idx >> 5, p = idx & 31;
        u32 vh = g_VH[(grow+s)*32 + p], vl = g_VL[(grow+s)*32 + p];
        *(u16*)(smem + CO_BH + (2*p)*CRS   + s*2) = (u16)(vh & 0xffff);
        *(u16*)(smem + CO_BH + (2*p+1)*CRS + s*2) = (u16)(vh >> 16);
        *(u16*)(smem + CO_BL + (2*p)*CRS   + s*2) = (u16)(vl & 0xffff);
        *(u16*)(smem + CO_BL + (2*p+1)*CRS + s*2) = (u16)(vl >> 16);
    }
    __syncthreads();

    // phase 3: acc += P @ GV
#pragma unroll
    for (int ko = 0; ko < 4; ++ko) {
        int kb = ko*32;
        u32 Ah[4], Al[4], Bb[4][2];
        u32 aoff = (u32)((warp_m*16 + laneA_row)*CRS + kb + laneA_kb);
        ldsm4(Ah[0], Ah[1], Ah[2], Ah[3], sb + CO_PH + aoff);
        ldsm4(Al[0], Al[1], Al[2], Al[3], sb + CO_PL + aoff);
#pragma unroll
        for (int np = 0; np < 2; ++np) {
            u32 boff = (u32)((warp_n*32 + np*16 + laneB_n)*CRS + kb + laneB_kb);
            ldsm4(Bb[2*np][0], Bb[2*np][1], Bb[2*np+1][0], Bb[2*np+1][1],
                  sb + CO_BH + boff);
        }
#pragma unroll
        for (int nt = 0; nt < 4; ++nt) mma_bf16(acc[nt], Ah, Bb[nt]);
#pragma unroll
        for (int nt = 0; nt < 4; ++nt) mma_bf16(acc[nt], Al, Bb[nt]);
#pragma unroll
        for (int np = 0; np < 2; ++np) {
            u32 boff = (u32)((warp_n*32 + np*16 + laneB_n)*CRS + kb + laneB_kb);
            ldsm4(Bb[2*np][0], Bb[2*np][1], Bb[2*np+1][0], Bb[2*np+1][1],
                  sb + CO_BL + boff);
        }
#pragma unroll
        for (int nt = 0; nt < 4; ++nt) mma_bf16(acc[nt], Ah, Bb[nt]);
    }

    // ---- write O pre-split ----
#pragma unroll
    for (int nt = 0; nt < 4; ++nt) {
        int j = warp_n*32 + nt*8 + t2*2;
        int pair = j >> 1;
        int i0 = warp_m*16 + g8;
        u32 hi, lo;
        split2(acc[nt][0], acc[nt][1], hi, lo);
        g_OH[(grow + i0)*32 + pair] = hi;
        g_OL[(grow + i0)*32 + pair] = lo;
        split2(acc[nt][2], acc[nt][3], hi, lo);
        g_OH[(grow + i0 + 8)*32 + pair] = hi;
        g_OL[(grow + i0 + 8)*32 + pair] = lo;
    }
}

// ---------- kernel 6: y = O @ Wo + bo (all operands pre-split, cp.async) ---
#define OH_OFF 0
#define OL_OFF 18432
#define WHO_OFF 36864
#define WLO_OFF 55296
#define OUT_SMEM 73728
#define ORS 144

__global__ void __launch_bounds__(256, 2) out_mma_kernel(
        const float* __restrict__ bo, float* __restrict__ y) {
    extern __shared__ char smem[];
    u32 sb = smem_u32(smem);
    int t = threadIdx.x;
    int lane = t & 31, wid = t >> 5;
    int warp_m = wid >> 1, warp_n = wid & 1;
    int r0 = blockIdx.x * 128;
    int n0 = blockIdx.y * 128;
    int blk = blockIdx.y;

    // Wo staging (pre-split)
#pragma unroll
    for (int p = 0; p < 4; ++p) {
        int idx = t + p*256;
        int row = idx >> 3, ch = idx & 7;
        cpasync16(sb + WHO_OFF + row*ORS + ch*16, g_WoH + ((blk*128 + row)*32 + ch*4));
        cpasync16(sb + WLO_OFF + row*ORS + ch*16, g_WoL + ((blk*128 + row)*32 + ch*4));
    }
    // O staging (pre-split)
#pragma unroll
    for (int p = 0; p < 4; ++p) {
        int idx = t + p*256;
        int row = idx >> 3, ch = idx & 7;
        cpasync16(sb + OH_OFF + row*ORS + ch*16, g_OH + ((size_t)(r0 + row)*32 + ch*4));
        cpasync16(sb + OL_OFF + row*ORS + ch*16, g_OL + ((size_t)(r0 + row)*32 + ch*4));
    }
    asm volatile("cp.async.commit_group;" ::: "memory");
    asm volatile("cp.async.wait_group 0;" ::: "memory");
    __syncthreads();

    int laneA_row = lane & 15;
    int laneA_kb  = (lane >> 4) * 16;
    int laneB_n   = (lane & 7) + ((lane >> 4) << 3);
    int laneB_kb  = ((lane >> 3) & 1) * 16;

    float acc[2][8][4];
#pragma unroll
    for (int i = 0; i < 2; ++i)
#pragma unroll
        for (int j = 0; j < 8; ++j)
#pragma unroll
            for (int k = 0; k < 4; ++k) acc[i][j][k] = 0.f;

#pragma unroll
    for (int ko = 0; ko < 4; ++ko) {
        int kb = ko*32;
        u32 Ah[2][4], Al[2][4], Bb[8][2];
#pragma unroll
        for (int mt = 0; mt < 2; ++mt) {
            u32 aoff = (u32)((warp_m*32 + mt*16 + laneA_row)*ORS + kb + laneA_kb);
            ldsm4(Ah[mt][0], Ah[mt][1], Ah[mt][2], Ah[mt][3], sb + OH_OFF + aoff);
            ldsm4(Al[mt][0], Al[mt][1], Al[mt][2], Al[mt][3], sb + OL_OFF + aoff);
        }
#pragma unroll
        for (int np = 0; np < 4; ++np) {
            u32 boff = (u32)((warp_n*64 + np*16 + laneB_n)*ORS + kb + laneB_kb);
            ldsm4(Bb[2*np][0], Bb[2*np][1], Bb[2*np+1][0], Bb[2*np+1][1],
                  sb + WHO_OFF + boff);
        }
#pragma unroll
        for (int mt = 0; mt < 2; ++mt)
#pragma unroll
            for (int nt = 0; nt < 8; ++nt) mma_bf16(acc[mt][nt], Ah[mt], Bb[nt]);
#pragma unroll
        for (int mt = 0; mt < 2; ++mt)
#pragma unroll
            for (int nt = 0; nt < 8; ++nt) mma_bf16(acc[mt][nt], Al[mt], Bb[nt]);
#pragma unroll
        for (int np = 0; np < 4; ++np) {
            u32 boff = (u32)((warp_n*64 + np*16 + laneB_n)*ORS + kb + laneB_kb);
            ldsm4(Bb[2*np][0], Bb[2*np][1], Bb[2*np+1][0], Bb[2*np+1][1],
                  sb + WLO_OFF + boff);
        }
#pragma unroll
        for (int mt = 0; mt < 2; ++mt)
#pragma unroll
            for (int nt = 0; nt < 8; ++nt) mma_bf16(acc[mt][nt], Ah[mt], Bb[nt]);
    }

    int g8 = lane >> 2, t2 = lane & 3;
#pragma unroll
    for (int mt = 0; mt < 2; ++mt) {
        int row = r0 + warp_m*32 + mt*16 + g8;
#pragma unroll
        for (int nt = 0; nt < 8; ++nt) {
            int col = n0 + warp_n*64 + nt*8 + t2*2;
            float2 bias = *(const float2*)(bo + col);
            *(float2*)(y + (size_t)row*D_ + col) =
                make_float2(acc[mt][nt][0] + bias.x, acc[mt][nt][1] + bias.y);
            *(float2*)(y + (size_t)(row + 8)*D_ + col) =
                make_float2(acc[mt][nt][2] + bias.x, acc[mt][nt][3] + bias.y);
        }
    }
}

// ---------------- launcher ----------------
extern "C" void kernel_launch(void* const* d_in, const int* in_sizes, int n_in,
                              void* d_out, int out_size) {
    const float* x  = (const float*)d_in[0];
    const float* Wq = (const float*)d_in[1];
    const float* Wk = (const float*)d_in[2];
    const float* Wv = (const float*)d_in[3];
    const float* Wo = (const float*)d_in[4];
    const float* bo = (const float*)d_in[5];
    const float* Wg = (const float*)d_in[6];
    const float* bg = (const float*)d_in[7];
    const float* dp = (const float*)d_in[8];
    float* y      = (float*)d_out;
    float* sfinal = y + (size_t)BL_ * D_;

    cudaFuncSetAttribute(qkv_mma_kernel,
                         cudaFuncAttributeMaxDynamicSharedMemorySize, QKV_SMEM);
    cudaFuncSetAttribute(out_mma_kernel,
                         cudaFuncAttributeMaxDynamicSharedMemorySize, OUT_SMEM);
    cudaFuncSetAttribute(chunk_sum_kernel,
                         cudaFuncAttributeMaxDynamicSharedMemorySize, CS_SMEM);
    cudaFuncSetAttribute(chunk_out_kernel,
                         cudaFuncAttributeMaxDynamicSharedMemorySize, CO_SMEM);

    wprep_kernel     <<<768, 256>>>(Wq, Wk, Wv);
    woprep_kernel    <<<128, 256>>>(Wo);
    qkv_mma_kernel   <<<BL_/64, 256, QKV_SMEM>>>(x, Wg, bg);
    chunk_sum_kernel <<<dim3(C_, B_), 256, CS_SMEM>>>(dp);
    chunk_scan_kernel<<<(B_*M_*M_)/256, 256>>>(dp, sfinal);
    chunk_out_kernel <<<dim3(C_, B_), 256, CO_SMEM>>>(dp);
    out_mma_kernel   <<<dim3(BL_/128, D_/128), 256, OUT_SMEM>>>(bo, y);
}

// round 12
// speedup vs baseline: 1.1785x; 1.1785x over previous
#include <cuda_runtime.h>
#include <cuda_bf16.h>
#include <cuda_fp16.h>
#include <cstdint>
#include <math.h>

#define B_  8
#define L_  4096
#define D_  1024
#define M_  64
#define BL_ (B_*L_)
#define C_  64
#define T_  64

typedef unsigned long long u64;
typedef unsigned int u32;
typedef unsigned short u16;

// ---------------- scratch ----------------
__device__ u32   g_QH[BL_*32], g_QL[BL_*32];   // Q  split-bf16 pairs
__device__ u32   g_KH[BL_*32], g_KL[BL_*32];   // gated K
__device__ u32   g_VH[BL_*32], g_VL[BL_*32];   // gated V
__device__ u32   g_OHf[BL_*32];                // O as fp16 pairs (single term)
__device__ float g_A   [B_*C_*M_*M_];          // A^T[j][i]
__device__ float g_Spre[B_*C_*M_*M_];          // Spre^T[j][m]
__device__ u16   g_Wh  [32*192*32];            // fp16 W hi  [it][n][k]
__device__ u16   g_Wl  [32*192*32];            // fp16 W lo
__device__ u32   g_WoH [8*128*32];             // fp16 Wo hi pairs
__device__ u32   g_WoL [8*128*32];             // fp16 Wo lo pairs

__device__ __forceinline__ float decay_val(const float* dp) {
    return 0.9f + 0.099f / (1.0f + expf(-dp[0]));
}

// ---- helpers ----
__device__ __forceinline__ u32 smem_u32(const void* p) {
    u32 a;
    asm("{ .reg .u64 t; cvta.to.shared.u64 t, %1; cvt.u32.u64 %0, t; }" : "=r"(a) : "l"(p));
    return a;
}
__device__ __forceinline__ void ldsm4(u32& r0, u32& r1, u32& r2, u32& r3, u32 a) {
    asm volatile("ldmatrix.sync.aligned.m8n8.x4.shared.b16 {%0,%1,%2,%3},[%4];"
                 : "=r"(r0), "=r"(r1), "=r"(r2), "=r"(r3) : "r"(a));
}
__device__ __forceinline__ void mma_bf16(float* d, const u32* a, const u32* b) {
    asm volatile(
        "mma.sync.aligned.m16n8k16.row.col.f32.bf16.bf16.f32 "
        "{%0,%1,%2,%3},{%4,%5,%6,%7},{%8,%9},{%0,%1,%2,%3};"
        : "+f"(d[0]), "+f"(d[1]), "+f"(d[2]), "+f"(d[3])
        : "r"(a[0]), "r"(a[1]), "r"(a[2]), "r"(a[3]), "r"(b[0]), "r"(b[1]));
}
__device__ __forceinline__ void mma_f16(float* d, const u32* a, const u32* b) {
    asm volatile(
        "mma.sync.aligned.m16n8k16.row.col.f32.f16.f16.f32 "
        "{%0,%1,%2,%3},{%4,%5,%6,%7},{%8,%9},{%0,%1,%2,%3};"
        : "+f"(d[0]), "+f"(d[1]), "+f"(d[2]), "+f"(d[3])
        : "r"(a[0]), "r"(a[1]), "r"(a[2]), "r"(a[3]), "r"(b[0]), "r"(b[1]));
}
__device__ __forceinline__ void split2(float x0, float x1, u32& hi, u32& lo) {
    __nv_bfloat162 h = __floats2bfloat162_rn(x0, x1);
    float r0 = x0 - __bfloat162float(h.x);
    float r1 = x1 - __bfloat162float(h.y);
    __nv_bfloat162 l = __floats2bfloat162_rn(r0, r1);
    hi = *(u32*)&h;  lo = *(u32*)&l;
}
__device__ __forceinline__ void split1(float x, u16& hi, u16& lo) {
    __nv_bfloat16 h = __float2bfloat16(x);
    __nv_bfloat16 l = __float2bfloat16(x - __bfloat162float(h));
    hi = *(u16*)&h;  lo = *(u16*)&l;
}
__device__ __forceinline__ void split1h(float x, u16& hi, u16& lo) {
    __half h = __float2half_rn(x);
    __half l = __float2half_rn(x - __half2float(h));
    hi = *(u16*)&h;  lo = *(u16*)&l;
}
__device__ __forceinline__ void split2h(float x0, float x1, u32& hi, u32& lo) {
    __half2 h = __floats2half2_rn(x0, x1);
    float r0 = x0 - __half2float(__low2half(h));
    float r1 = x1 - __half2float(__high2half(h));
    __half2 l = __floats2half2_rn(r0, r1);
    hi = *(u32*)&h;  lo = *(u32*)&l;
}
__device__ __forceinline__ u32 pack_h2(float x0, float x1) {
    __half2 h = __floats2half2_rn(x0, x1);
    return *(u32*)&h;
}
__device__ __forceinline__ float bflo(u32 v) {
    u16 h = (u16)(v & 0xffff);
    return __bfloat162float(*(__nv_bfloat16*)&h);
}
__device__ __forceinline__ float bfhi(u32 v) {
    u16 h = (u16)(v >> 16);
    return __bfloat162float(*(__nv_bfloat16*)&h);
}
__device__ __forceinline__ void cpasync16(u32 dst, const void* src) {
    asm volatile("cp.async.cg.shared.global [%0], [%1], 16;" :: "r"(dst), "l"(src));
}

// ---------- kernel 0a: W prep (fp16 split) ----------
__global__ void wprep_kernel(const float* __restrict__ Wq,
                             const float* __restrict__ Wk,
                             const float* __restrict__ Wv) {
    int idx = blockIdx.x*256 + threadIdx.x;
    int kk = idx & 31;
    int r  = idx >> 5;
    int n  = r % 192;
    int it = r / 192;
    int col = n & 63;
    const float* Wp = (n < 64) ? Wq : (n < 128) ? Wk : Wv;
    float w = Wp[(size_t)(it*32 + kk)*M_ + col];
    u16 hi, lo;
    split1h(w, hi, lo);
    g_Wh[idx] = hi;
    g_Wl[idx] = lo;
}

// ---------- kernel 0b: Wo prep (fp16 split pairs) ----------
__global__ void woprep_kernel(const float* __restrict__ Wo) {
    int idx = blockIdx.x*256 + threadIdx.x;
    int kp = idx & 31;
    int n  = (idx >> 5) & 127;
    int blk = idx >> 12;
    int ng = blk*128 + n;
    u32 hi, lo;
    split2h(Wo[(size_t)(2*kp)*D_ + ng], Wo[(size_t)(2*kp+1)*D_ + ng], hi, lo);
    g_WoH[idx] = hi;
    g_WoL[idx] = lo;
}

// SMEM layout for qkv: X single fp16 (no lo), double-buffered. Row stride 80B.
#define RS 80
#define XHo(b)  ((b)*5120)
#define WHo(b)  (10240 + (b)*15360)
#define WLo(b)  (40960 + (b)*15360)
#define WGV_OFF 71680
#define GATE_OFF 75776
#define QKV_SMEM 76288

// ========== kernel 1: fused QKV+gate, fp16 2-term, 2 CTAs/SM ====
__global__ void __launch_bounds__(256, 2) qkv_mma_kernel(
        const float* __restrict__ x,
        const float* __restrict__ Wg, const float* __restrict__ bg) {
    extern __shared__ char smem[];
    u32 sb = smem_u32(smem);
    int t = threadIdx.x;
    int lane = t & 31, wid = t >> 5;
    int warp_m = wid >> 2, warp_n = wid & 3;
    int r0 = blockIdx.x * 64;

    *(float4*)(smem + WGV_OFF + t*16) = *(const float4*)(Wg + t*4);
    const float* wgs = (const float*)(smem + WGV_OFF);

    int rowX = t >> 3;
    int c4   = t & 7;

    int wn[6], wc[6], wterm[6];
#pragma unroll
    for (int rr = 0; rr < 6; ++rr) {
        int idx = t + rr*256;
        wterm[rr] = (idx >= 768);
        int rem = idx - wterm[rr]*768;
        wn[rr] = rem >> 2;
        wc[rr] = rem & 3;
    }

    int laneA_row = lane & 15;
    int laneA_kb  = (lane >> 4) * 16;
    int laneB_n   = (lane & 7) + ((lane >> 4) << 3);
    int laneB_kb  = ((lane >> 3) & 1) * 16;

    float acc[2][6][4];
#pragma unroll
    for (int i = 0; i < 2; ++i)
#pragma unroll
        for (int j = 0; j < 6; ++j)
#pragma unroll
            for (int k = 0; k < 4; ++k) acc[i][j][k] = 0.f;
    float gacc[2] = {0.f, 0.f};

    __syncthreads();

    float4 xr0 = *(const float4*)(x + (size_t)(r0 + rowX)*D_ + c4*4);
    float4 xr1 = *(const float4*)(x + (size_t)(r0 + rowX + 32)*D_ + c4*4);
#pragma unroll
    for (int rr = 0; rr < 6; ++rr) {
        u32 dst = sb + (wterm[rr] ? WLo(0) : WHo(0)) + wn[rr]*RS + wc[rr]*16;
        const u16* src = (wterm[rr] ? g_Wl : g_Wh) + ((0*192 + wn[rr])*32 + wc[rr]*8);
        cpasync16(dst, src);
    }
    asm volatile("cp.async.commit_group;" ::: "memory");

#pragma unroll 1
    for (int it = 0; it < 32; ++it) {
        int buf = it & 1;
        int k0 = it * 32;
        {
            const float* wg4 = wgs + k0 + c4*4;
            gacc[0] += xr0.x*wg4[0] + xr0.y*wg4[1] + xr0.z*wg4[2] + xr0.w*wg4[3];
            gacc[1] += xr1.x*wg4[0] + xr1.y*wg4[1] + xr1.z*wg4[2] + xr1.w*wg4[3];
            u32 a0 = pack_h2(xr0.x, xr0.y), a1 = pack_h2(xr0.z, xr0.w);
            *(u64*)(smem + XHo(buf) + rowX*RS + c4*8) = ((u64)a1 << 32) | a0;
            a0 = pack_h2(xr1.x, xr1.y);  a1 = pack_h2(xr1.z, xr1.w);
            *(u64*)(smem + XHo(buf) + (rowX+32)*RS + c4*8) = ((u64)a1 << 32) | a0;
        }
        asm volatile("cp.async.wait_group 0;" ::: "memory");
        __syncthreads();
        if (it < 31) {
            int k1 = k0 + 32;
            xr0 = *(const float4*)(x + (size_t)(r0 + rowX)*D_ + k1 + c4*4);
            xr1 = *(const float4*)(x + (size_t)(r0 + rowX + 32)*D_ + k1 + c4*4);
#pragma unroll
            for (int rr = 0; rr < 6; ++rr) {
                u32 dst = sb + (wterm[rr] ? WLo(buf^1) : WHo(buf^1)) + wn[rr]*RS + wc[rr]*16;
                const u16* src = (wterm[rr] ? g_Wl : g_Wh)
                               + (((it+1)*192 + wn[rr])*32 + wc[rr]*8);
                cpasync16(dst, src);
            }
            asm volatile("cp.async.commit_group;" ::: "memory");
        }
#pragma unroll
        for (int ko = 0; ko < 2; ++ko) {
            int kb = ko*32;
            u32 Ah[2][4], Bb[6][2];
#pragma unroll
            for (int mt = 0; mt < 2; ++mt) {
                u32 aoff = (u32)((warp_m*32 + mt*16 + laneA_row)*RS + kb + laneA_kb);
                ldsm4(Ah[mt][0], Ah[mt][1], Ah[mt][2], Ah[mt][3], sb + XHo(buf) + aoff);
            }
#pragma unroll
            for (int np = 0; np < 3; ++np) {
                u32 boff = (u32)((warp_n*48 + np*16 + laneB_n)*RS + kb + laneB_kb);
                ldsm4(Bb[2*np][0], Bb[2*np][1], Bb[2*np+1][0], Bb[2*np+1][1],
                      sb + WHo(buf) + boff);
            }
#pragma unroll
            for (int mt = 0; mt < 2; ++mt)
#pragma unroll
                for (int nt = 0; nt < 6; ++nt) mma_f16(acc[mt][nt], Ah[mt], Bb[nt]);
#pragma unroll
            for (int np = 0; np < 3; ++np) {
                u32 boff = (u32)((warp_n*48 + np*16 + laneB_n)*RS + kb + laneB_kb);
                ldsm4(Bb[2*np][0], Bb[2*np][1], Bb[2*np+1][0], Bb[2*np+1][1],
                      sb + WLo(buf) + boff);
            }
#pragma unroll
            for (int mt = 0; mt < 2; ++mt)
#pragma unroll
                for (int nt = 0; nt < 6; ++nt) mma_f16(acc[mt][nt], Ah[mt], Bb[nt]);
        }
    }

#pragma unroll
    for (int off = 4; off; off >>= 1)
#pragma unroll
        for (int rep = 0; rep < 2; ++rep)
            gacc[rep] += __shfl_xor_sync(0xffffffffu, gacc[rep], off);
    if ((t & 7) == 0) {
        float bgv = bg[0];
        ((float*)(smem + GATE_OFF))[rowX]      = 1.0f/(1.0f + expf(-(gacc[0] + bgv)));
        ((float*)(smem + GATE_OFF))[rowX + 32] = 1.0f/(1.0f + expf(-(gacc[1] + bgv)));
    }
    __syncthreads();
    const float* gate = (const float*)(smem + GATE_OFF);

    // epilogue: split-bf16 Q / gated-K / gated-V (downstream unchanged)
    int g8 = lane >> 2, t2 = lane & 3;
#pragma unroll
    for (int mt = 0; mt < 2; ++mt) {
        int rl0 = warp_m*32 + mt*16 + g8;
#pragma unroll
        for (int nt = 0; nt < 6; ++nt) {
            int col = warp_n*48 + nt*8 + t2*2;
            int proj = col >> 6, pair = (col & 63) >> 1;
            u32* OutH = (proj == 0) ? g_QH : (proj == 1) ? g_KH : g_VH;
            u32* OutL = (proj == 0) ? g_QL : (proj == 1) ? g_KL : g_VL;
            float ga = (proj == 0) ? 1.0f : gate[rl0];
            float gb = (proj == 0) ? 1.0f : gate[rl0 + 8];
            u32 hi, lo;
            split2(acc[mt][nt][0]*ga, acc[mt][nt][1]*ga, hi, lo);
            OutH[(size_t)(r0 + rl0)*32 + pair] = hi;
            OutL[(size_t)(r0 + rl0)*32 + pair] = lo;
            split2(acc[mt][nt][2]*gb, acc[mt][nt][3]*gb, hi, lo);
            OutH[(size_t)(r0 + rl0 + 8)*32 + pair] = hi;
            OutL[(size_t)(r0 + rl0 + 8)*32 + pair] = lo;
        }
    }
}

// ---- chunk constants ----
#define CRS 144

// --------- kernel 3: chunk summaries -> A^T (bf16 3-term) -------------------
#define CS_AH 0
#define CS_AL 9216
#define CS_BH 18432
#define CS_BL 27648
#define CS_DP 36864
#define CS_SMEM 37376

__global__ void __launch_bounds__(256) chunk_sum_kernel(const float* __restrict__ dp) {
    extern __shared__ char smem[];
    u32 sb = smem_u32(smem);
    int b = blockIdx.y, c = blockIdx.x;
    int t = threadIdx.x, lane = t & 31, wid = t >> 5;
    int warp_m = wid >> 1, warp_n = wid & 1;
    float d = decay_val(dp);
    float* dpow = (float*)(smem + CS_DP);
    if (t < 64) dpow[t] = powf(d, (float)t);
    __syncthreads();

    size_t grow = (size_t)b*L_ + (size_t)c*T_;
#pragma unroll
    for (int rep = 0; rep < 8; ++rep) {
        int idx = t + rep*256;
        int s = idx >> 5, p = idx & 31;
        u32 kh = g_KH[(grow+s)*32 + p], kl = g_KL[(grow+s)*32 + p];
        u32 vh = g_VH[(grow+s)*32 + p], vl = g_VL[(grow+s)*32 + p];
        float w = dpow[63 - s];
        *(u16*)(smem + CS_AH + (2*p)*CRS   + s*2) = (u16)(vh & 0xffff);
        *(u16*)(smem + CS_AH + (2*p+1)*CRS + s*2) = (u16)(vh >> 16);
        *(u16*)(smem + CS_AL + (2*p)*CRS   + s*2) = (u16)(vl & 0xffff);
        *(u16*)(smem + CS_AL + (2*p+1)*CRS + s*2) = (u16)(vl >> 16);
        float f0 = (bflo(kh) + bflo(kl)) * w;
        float f1 = (bfhi(kh) + bfhi(kl)) * w;
        u16 hi, lo;
        split1(f0, hi, lo);
        *(u16*)(smem + CS_BH + (2*p)*CRS + s*2) = hi;
        *(u16*)(smem + CS_BL + (2*p)*CRS + s*2) = lo;
        split1(f1, hi, lo);
        *(u16*)(smem + CS_BH + (2*p+1)*CRS + s*2) = hi;
        *(u16*)(smem + CS_BL + (2*p+1)*CRS + s*2) = lo;
    }
    __syncthreads();

    int laneA_row = lane & 15;
    int laneA_kb  = (lane >> 4) * 16;
    int laneB_n   = (lane & 7) + ((lane >> 4) << 3);
    int laneB_kb  = ((lane >> 3) & 1) * 16;

    float acc[4][4];
#pragma unroll
    for (int j = 0; j < 4; ++j)
#pragma unroll
        for (int k = 0; k < 4; ++k) acc[j][k] = 0.f;

#pragma unroll
    for (int ko = 0; ko < 4; ++ko) {
        int kb = ko*32;
        u32 Ah[4], Al[4], Bb[4][2];
        u32 aoff = (u32)((warp_m*16 + laneA_row)*CRS + kb + laneA_kb);
        ldsm4(Ah[0], Ah[1], Ah[2], Ah[3], sb + CS_AH + aoff);
        ldsm4(Al[0], Al[1], Al[2], Al[3], sb + CS_AL + aoff);
#pragma unroll
        for (int np = 0; np < 2; ++np) {
            u32 boff = (u32)((warp_n*32 + np*16 + laneB_n)*CRS + kb + laneB_kb);
            ldsm4(Bb[2*np][0], Bb[2*np][1], Bb[2*np+1][0], Bb[2*np+1][1],
                  sb + CS_BH + boff);
        }
#pragma unroll
        for (int nt = 0; nt < 4; ++nt) mma_bf16(acc[nt], Ah, Bb[nt]);
#pragma unroll
        for (int nt = 0; nt < 4; ++nt) mma_bf16(acc[nt], Al, Bb[nt]);
#pragma unroll
        for (int np = 0; np < 2; ++np) {
            u32 boff = (u32)((warp_n*32 + np*16 + laneB_n)*CRS + kb + laneB_kb);
            ldsm4(Bb[2*np][0], Bb[2*np][1], Bb[2*np+1][0], Bb[2*np+1][1],
                  sb + CS_BL + boff);
        }
#pragma unroll
        for (int nt = 0; nt < 4; ++nt) mma_bf16(acc[nt], Ah, Bb[nt]);
    }

    int g8 = lane >> 2, t2 = lane & 3;
    size_t ab = (size_t)(b*C_ + c) * (M_*M_);
#pragma unroll
    for (int nt = 0; nt < 4; ++nt) {
        int j = warp_n*32 + nt*8 + t2*2;
        int i0 = warp_m*16 + g8;
        *(float2*)(g_A + ab + (size_t)i0*M_ + j)     = make_float2(acc[nt][0], acc[nt][1]);
        *(float2*)(g_A + ab + (size_t)(i0+8)*M_ + j) = make_float2(acc[nt][2], acc[nt][3]);
    }
}

// --------- kernel 4: inter-chunk scan (transposed; MLP-8) ----------
__global__ void chunk_scan_kernel(const float* __restrict__ dp,
                                  float* __restrict__ sfinal) {
    int gid = blockIdx.x * blockDim.x + threadIdx.x;
    int b = gid >> 12;
    int e = gid & 4095;
    float d  = decay_val(dp);
    float dT = powf(d, 64.0f);
    float S = 0.f;
#pragma unroll 1
    for (int c0 = 0; c0 < C_; c0 += 8) {
        float a[8];
#pragma unroll
        for (int j = 0; j < 8; ++j)
            a[j] = g_A[((size_t)(b*C_ + c0 + j) << 12) + e];
#pragma unroll
        for (int j = 0; j < 8; ++j) {
            g_Spre[((size_t)(b*C_ + c0 + j) << 12) + e] = S;
            S = dT*S + a[j];
        }
    }
    sfinal[((size_t)b << 12) + (e & 63)*64 + (e >> 6)] = S;
}

// --------- kernel 5: per-chunk outputs (bf16 3-term; O -> fp16) ------------
#define CO_QH 0
#define CO_QL 9216
#define CO_PH 18432
#define CO_PL 27648
#define CO_BH 36864
#define CO_BL 46080
#define CO_DP 55296
#define CO_SMEM 55808

__global__ void __launch_bounds__(256) chunk_out_kernel(const float* __restrict__ dp) {
    extern __shared__ char smem[];
    u32 sb = smem_u32(smem);
    int b = blockIdx.y, c = blockIdx.x;
    int t = threadIdx.x, lane = t & 31, wid = t >> 5;
    int warp_m = wid >> 1, warp_n = wid & 1;
    float d = decay_val(dp);
    float* dpow = (float*)(smem + CO_DP);
    if (t < 65) dpow[t] = powf(d, (float)t);

    size_t grow = (size_t)b*L_ + (size_t)c*T_;
    size_t sbase = (size_t)(b*C_ + c) * (M_*M_);

#pragma unroll
    for (int rep = 0; rep < 2; ++rep) {
        int idx = t + rep*256;
        int row = idx >> 3, ch = idx & 7;
        u32 off = row*CRS + ch*16;
        cpasync16(sb + CO_QH + off, g_QH + (grow + row)*32 + ch*4);
        cpasync16(sb + CO_QL + off, g_QL + (grow + row)*32 + ch*4);
        cpasync16(sb + CO_BH + off, g_KH + (grow + row)*32 + ch*4);
        cpasync16(sb + CO_BL + off, g_KL + (grow + row)*32 + ch*4);
    }
    asm volatile("cp.async.commit_group;" ::: "memory");
    asm volatile("cp.async.wait_group 0;" ::: "memory");
    __syncthreads();

    int laneA_row = lane & 15;
    int laneA_kb  = (lane >> 4) * 16;
    int laneB_n   = (lane & 7) + ((lane >> 4) << 3);
    int laneB_kb  = ((lane >> 3) & 1) * 16;
    int g8 = lane >> 2, t2 = lane & 3;

    // phase 1: P = Q @ GK^T
    float pacc[4][4];
#pragma unroll
    for (int j = 0; j < 4; ++j)
#pragma unroll
        for (int k = 0; k < 4; ++k) pacc[j][k] = 0.f;
#pragma unroll
    for (int ko = 0; ko < 4; ++ko) {
        int kb = ko*32;
        u32 Ah[4], Al[4], Bb[4][2];
        u32 aoff = (u32)((warp_m*16 + laneA_row)*CRS + kb + laneA_kb);
        ldsm4(Ah[0], Ah[1], Ah[2], Ah[3], sb + CO_QH + aoff);
        ldsm4(Al[0], Al[1], Al[2], Al[3], sb + CO_QL + aoff);
#pragma unroll
        for (int np = 0; np < 2; ++np) {
            u32 boff = (u32)((warp_n*32 + np*16 + laneB_n)*CRS + kb + laneB_kb);
            ldsm4(Bb[2*np][0], Bb[2*np][1], Bb[2*np+1][0], Bb[2*np+1][1],
                  sb + CO_BH + boff);
        }
#pragma unroll
        for (int nt = 0; nt < 4; ++nt) mma_bf16(pacc[nt], Ah, Bb[nt]);
#pragma unroll
        for (int nt = 0; nt < 4; ++nt) mma_bf16(pacc[nt], Al, Bb[nt]);
#pragma unroll
        for (int np = 0; np < 2; ++np) {
            u32 boff = (u32)((warp_n*32 + np*16 + laneB_n)*CRS + kb + laneB_kb);
            ldsm4(Bb[2*np][0], Bb[2*np][1], Bb[2*np+1][0], Bb[2*np+1][1],
                  sb + CO_BL + boff);
        }
#pragma unroll
        for (int nt = 0; nt < 4; ++nt) mma_bf16(pacc[nt], Ah, Bb[nt]);
    }
#pragma unroll
    for (int nt = 0; nt < 4; ++nt) {
        int colb = warp_n*32 + nt*8 + t2*2;
        int ra = warp_m*16 + g8;
        float p0 = (colb   <= ra) ? pacc[nt][0]*dpow[ra - colb]     : 0.f;
        float p1 = (colb+1 <= ra) ? pacc[nt][1]*dpow[ra - colb - 1] : 0.f;
        int rb = ra + 8;
        float p2 = (colb   <= rb) ? pacc[nt][2]*dpow[rb - colb]     : 0.f;
        float p3 = (colb+1 <= rb) ? pacc[nt][3]*dpow[rb - colb - 1] : 0.f;
        u32 hi, lo;
        split2(p0, p1, hi, lo);
        *(u32*)(smem + CO_PH + ra*CRS + colb*2) = hi;
        *(u32*)(smem + CO_PL + ra*CRS + colb*2) = lo;
        split2(p2, p3, hi, lo);
        *(u32*)(smem + CO_PH + rb*CRS + colb*2) = hi;
        *(u32*)(smem + CO_PL + rb*CRS + colb*2) = lo;
    }
    __syncthreads();

    // stage Spre^T (natural fp32)
#pragma unroll
    for (int rep = 0; rep < 4; ++rep) {
        int idx = t + rep*256;
        int row = idx >> 4, c4 = idx & 15;
        float4 v = *(const float4*)(g_Spre + sbase + (size_t)row*M_ + c4*4);
        u32 h0,l0,h1,l1;
        split2(v.x, v.y, h0, l0);
        split2(v.z, v.w, h1, l1);
        int off = row*CRS + c4*8;
        *(u32*)(smem + CO_BH + off)   = h0;
        *(u32*)(smem + CO_BH + off+4) = h1;
        *(u32*)(smem + CO_BL + off)   = l0;
        *(u32*)(smem + CO_BL + off+4) = l1;
    }
    __syncthreads();

    // phase 2: acc = Q @ Spre
    float acc[4][4];
#pragma unroll
    for (int j = 0; j < 4; ++j)
#pragma unroll
        for (int k = 0; k < 4; ++k) acc[j][k] = 0.f;
#pragma unroll
    for (int ko = 0; ko < 4; ++ko) {
        int kb = ko*32;
        u32 Ah[4], Al[4], Bb[4][2];
        u32 aoff = (u32)((warp_m*16 + laneA_row)*CRS + kb + laneA_kb);
        ldsm4(Ah[0], Ah[1], Ah[2], Ah[3], sb + CO_QH + aoff);
        ldsm4(Al[0], Al[1], Al[2], Al[3], sb + CO_QL + aoff);
#pragma unroll
        for (int np = 0; np < 2; ++np) {
            u32 boff = (u32)((warp_n*32 + np*16 + laneB_n)*CRS + kb + laneB_kb);
            ldsm4(Bb[2*np][0], Bb[2*np][1], Bb[2*np+1][0], Bb[2*np+1][1],
                  sb + CO_BH + boff);
        }
#pragma unroll
        for (int nt = 0; nt < 4; ++nt) mma_bf16(acc[nt], Ah, Bb[nt]);
#pragma unroll
        for (int nt = 0; nt < 4; ++nt) mma_bf16(acc[nt], Al, Bb[nt]);
#pragma unroll
        for (int np = 0; np < 2; ++np) {
            u32 boff = (u32)((warp_n*32 + np*16 + laneB_n)*CRS + kb + laneB_kb);
            ldsm4(Bb[2*np][0], Bb[2*np][1], Bb[2*np+1][0], Bb[2*np+1][1],
                  sb + CO_BL + boff);
        }
#pragma unroll
        for (int nt = 0; nt < 4; ++nt) mma_bf16(acc[nt], Ah, Bb[nt]);
    }
    {
        int ra = warp_m*16 + g8;
        float sa = dpow[ra + 1], sbc = dpow[ra + 9];
#pragma unroll
        for (int nt = 0; nt < 4; ++nt) {
            acc[nt][0] *= sa;  acc[nt][1] *= sa;
            acc[nt][2] *= sbc; acc[nt][3] *= sbc;
        }
    }
    __syncthreads();

    // stage GV^T from pre-split pairs
#pragma unroll
    for (int rep = 0; rep < 8; ++rep) {
        int idx = t + rep*256;
        int s = idx >> 5, p = idx & 31;
        u32 vh = g_VH[(grow+s)*32 + p], vl = g_VL[(grow+s)*32 + p];
        *(u16*)(smem + CO_BH + (2*p)*CRS   + s*2) = (u16)(vh & 0xffff);
        *(u16*)(smem + CO_BH + (2*p+1)*CRS + s*2) = (u16)(vh >> 16);
        *(u16*)(smem + CO_BL + (2*p)*CRS   + s*2) = (u16)(vl & 0xffff);
        *(u16*)(smem + CO_BL + (2*p+1)*CRS + s*2) = (u16)(vl >> 16);
    }
    __syncthreads();

    // phase 3: acc += P @ GV
#pragma unroll
    for (int ko = 0; ko < 4; ++ko) {
        int kb = ko*32;
        u32 Ah[4], Al[4], Bb[4][2];
        u32 aoff = (u32)((warp_m*16 + laneA_row)*CRS + kb + laneA_kb);
        ldsm4(Ah[0], Ah[1], Ah[2], Ah[3], sb + CO_PH + aoff);
        ldsm4(Al[0], Al[1], Al[2], Al[3], sb + CO_PL + aoff);
#pragma unroll
        for (int np = 0; np < 2; ++np) {
            u32 boff = (u32)((warp_n*32 + np*16 + laneB_n)*CRS + kb + laneB_kb);
            ldsm4(Bb[2*np][0], Bb[2*np][1], Bb[2*np+1][0], Bb[2*np+1][1],
                  sb + CO_BH + boff);
        }
#pragma unroll
        for (int nt = 0; nt < 4; ++nt) mma_bf16(acc[nt], Ah, Bb[nt]);
#pragma unroll
        for (int nt = 0; nt < 4; ++nt) mma_bf16(acc[nt], Al, Bb[nt]);
#pragma unroll
        for (int np = 0; np < 2; ++np) {
            u32 boff = (u32)((warp_n*32 + np*16 + laneB_n)*CRS + kb + laneB_kb);
            ldsm4(Bb[2*np][0], Bb[2*np][1], Bb[2*np+1][0], Bb[2*np+1][1],
                  sb + CO_BL + boff);
        }
#pragma unroll
        for (int nt = 0; nt < 4; ++nt) mma_bf16(acc[nt], Ah, Bb[nt]);
    }

    // ---- write O as fp16 pairs ----
#pragma unroll
    for (int nt = 0; nt < 4; ++nt) {
        int j = warp_n*32 + nt*8 + t2*2;
        int pair = j >> 1;
        int i0 = warp_m*16 + g8;
        g_OHf[(grow + i0)*32 + pair]     = pack_h2(acc[nt][0], acc[nt][1]);
        g_OHf[(grow + i0 + 8)*32 + pair] = pack_h2(acc[nt][2], acc[nt][3]);
    }
}

// ---------- kernel 6: y = O @ Wo + bo (fp16 2-term) ----------
#define OH_OFF 0
#define WHO_OFF 18432
#define WLO_OFF 36864
#define OUT_SMEM 55296
#define ORS 144

__global__ void __launch_bounds__(256, 2) out_mma_kernel(
        const float* __restrict__ bo, float* __restrict__ y) {
    extern __shared__ char smem[];
    u32 sb = smem_u32(smem);
    int t = threadIdx.x;
    int lane = t & 31, wid = t >> 5;
    int warp_m = wid >> 1, warp_n = wid & 1;
    int r0 = blockIdx.x * 128;
    int n0 = blockIdx.y * 128;
    int blk = blockIdx.y;

#pragma unroll
    for (int p = 0; p < 4; ++p) {
        int idx = t + p*256;
        int row = idx >> 3, ch = idx & 7;
        cpasync16(sb + WHO_OFF + row*ORS + ch*16, g_WoH + ((blk*128 + row)*32 + ch*4));
        cpasync16(sb + WLO_OFF + row*ORS + ch*16, g_WoL + ((blk*128 + row)*32 + ch*4));
        cpasync16(sb + OH_OFF + row*ORS + ch*16, g_OHf + ((size_t)(r0 + row)*32 + ch*4));
    }
    asm volatile("cp.async.commit_group;" ::: "memory");
    asm volatile("cp.async.wait_group 0;" ::: "memory");
    __syncthreads();

    int laneA_row = lane & 15;
    int laneA_kb  = (lane >> 4) * 16;
    int laneB_n   = (lane & 7) + ((lane >> 4) << 3);
    int laneB_kb  = ((lane >> 3) & 1) * 16;

    float acc[2][8][4];
#pragma unroll
    for (int i = 0; i < 2; ++i)
#pragma unroll
        for (int j = 0; j < 8; ++j)
#pragma unroll
            for (int k = 0; k < 4; ++k) acc[i][j][k] = 0.f;

#pragma unroll
    for (int ko = 0; ko < 4; ++ko) {
        int kb = ko*32;
        u32 Ah[2][4], Bb[8][2];
#pragma unroll
        for (int mt = 0; mt < 2; ++mt) {
            u32 aoff = (u32)((warp_m*32 + mt*16 + laneA_row)*ORS + kb + laneA_kb);
            ldsm4(Ah[mt][0], Ah[mt][1], Ah[mt][2], Ah[mt][3], sb + OH_OFF + aoff);
        }
#pragma unroll
        for (int np = 0; np < 4; ++np) {
            u32 boff = (u32)((warp_n*64 + np*16 + laneB_n)*ORS + kb + laneB_kb);
            ldsm4(Bb[2*np][0], Bb[2*np][1], Bb[2*np+1][0], Bb[2*np+1][1],
                  sb + WHO_OFF + boff);
        }
#pragma unroll
        for (int mt = 0; mt < 2; ++mt)
#pragma unroll
            for (int nt = 0; nt < 8; ++nt) mma_f16(acc[mt][nt], Ah[mt], Bb[nt]);
#pragma unroll
        for (int np = 0; np < 4; ++np) {
            u32 boff = (u32)((warp_n*64 + np*16 + laneB_n)*ORS + kb + laneB_kb);
            ldsm4(Bb[2*np][0], Bb[2*np][1], Bb[2*np+1][0], Bb[2*np+1][1],
                  sb + WLO_OFF + boff);
        }
#pragma unroll
        for (int mt = 0; mt < 2; ++mt)
#pragma unroll
            for (int nt = 0; nt < 8; ++nt) mma_f16(acc[mt][nt], Ah[mt], Bb[nt]);
    }

    int g8 = lane >> 2, t2 = lane & 3;
#pragma unroll
    for (int mt = 0; mt < 2; ++mt) {
        int row = r0 + warp_m*32 + mt*16 + g8;
#pragma unroll
        for (int nt = 0; nt < 8; ++nt) {
            int col = n0 + warp_n*64 + nt*8 + t2*2;
            float2 bias = *(const float2*)(bo + col);
            *(float2*)(y + (size_t)row*D_ + col) =
                make_float2(acc[mt][nt][0] + bias.x, acc[mt][nt][1] + bias.y);
            *(float2*)(y + (size_t)(row + 8)*D_ + col) =
                make_float2(acc[mt][nt][2] + bias.x, acc[mt][nt][3] + bias.y);
        }
    }
}

// ---------------- launcher ----------------
extern "C" void kernel_launch(void* const* d_in, const int* in_sizes, int n_in,
                              void* d_out, int out_size) {
    const float* x  = (const float*)d_in[0];
    const float* Wq = (const float*)d_in[1];
    const float* Wk = (const float*)d_in[2];
    const float* Wv = (const float*)d_in[3];
    const float* Wo = (const float*)d_in[4];
    const float* bo = (const float*)d_in[5];
    const float* Wg = (const float*)d_in[6];
    const float* bg = (const float*)d_in[7];
    const float* dp = (const float*)d_in[8];
    float* y      = (float*)d_out;
    float* sfinal = y + (size_t)BL_ * D_;

    cudaFuncSetAttribute(qkv_mma_kernel,
                         cudaFuncAttributeMaxDynamicSharedMemorySize, QKV_SMEM);
    cudaFuncSetAttribute(out_mma_kernel,
                         cudaFuncAttributeMaxDynamicSharedMemorySize, OUT_SMEM);
    cudaFuncSetAttribute(chunk_sum_kernel,
                         cudaFuncAttributeMaxDynamicSharedMemorySize, CS_SMEM);
    cudaFuncSetAttribute(chunk_out_kernel,
                         cudaFuncAttributeMaxDynamicSharedMemorySize, CO_SMEM);

    wprep_kernel     <<<768, 256>>>(Wq, Wk, Wv);
    woprep_kernel    <<<128, 256>>>(Wo);
    qkv_mma_kernel   <<<BL_/64, 256, QKV_SMEM>>>(x, Wg, bg);
    chunk_sum_kernel <<<dim3(C_, B_), 256, CS_SMEM>>>(dp);
    chunk_scan_kernel<<<(B_*M_*M_)/256, 256>>>(dp, sfinal);
    chunk_out_kernel <<<dim3(C_, B_), 256, CO_SMEM>>>(dp);
    out_mma_kernel   <<<dim3(BL_/128, D_/128), 256, OUT_SMEM>>>(bo, y);
}

// round 13
// speedup vs baseline: 1.2250x; 1.0395x over previous
#include <cuda_runtime.h>
#include <cuda_bf16.h>
#include <cuda_fp16.h>
#include <cstdint>
#include <math.h>

#define B_  8
#define L_  4096
#define D_  1024
#define M_  64
#define BL_ (B_*L_)
#define C_  64
#define T_  64

typedef unsigned long long u64;
typedef unsigned int u32;
typedef unsigned short u16;

// ---------------- scratch ----------------
__device__ u32   g_QH[BL_*32], g_QL[BL_*32];
__device__ u32   g_KH[BL_*32], g_KL[BL_*32];
__device__ u32   g_VH[BL_*32], g_VL[BL_*32];
__device__ u32   g_OHf[BL_*32];
__device__ float g_A   [B_*C_*M_*M_];          // A^T[j][i]
__device__ float g_Spre[B_*C_*M_*M_];          // Spre^T[j][m]
__device__ u16   g_Wh  [32*192*32];
__device__ u16   g_Wl  [32*192*32];
__device__ u32   g_WoH [8*128*32];
__device__ u32   g_WoL [8*128*32];

__device__ __forceinline__ float decay_val(const float* dp) {
    return 0.9f + 0.099f / (1.0f + expf(-dp[0]));
}

// ---- helpers ----
__device__ __forceinline__ u32 smem_u32(const void* p) {
    u32 a;
    asm("{ .reg .u64 t; cvta.to.shared.u64 t, %1; cvt.u32.u64 %0, t; }" : "=r"(a) : "l"(p));
    return a;
}
__device__ __forceinline__ void ldsm4(u32& r0, u32& r1, u32& r2, u32& r3, u32 a) {
    asm volatile("ldmatrix.sync.aligned.m8n8.x4.shared.b16 {%0,%1,%2,%3},[%4];"
                 : "=r"(r0), "=r"(r1), "=r"(r2), "=r"(r3) : "r"(a));
}
__device__ __forceinline__ void mma_bf16(float* d, const u32* a, const u32* b) {
    asm volatile(
        "mma.sync.aligned.m16n8k16.row.col.f32.bf16.bf16.f32 "
        "{%0,%1,%2,%3},{%4,%5,%6,%7},{%8,%9},{%0,%1,%2,%3};"
        : "+f"(d[0]), "+f"(d[1]), "+f"(d[2]), "+f"(d[3])
        : "r"(a[0]), "r"(a[1]), "r"(a[2]), "r"(a[3]), "r"(b[0]), "r"(b[1]));
}
__device__ __forceinline__ void mma_f16(float* d, const u32* a, const u32* b) {
    asm volatile(
        "mma.sync.aligned.m16n8k16.row.col.f32.f16.f16.f32 "
        "{%0,%1,%2,%3},{%4,%5,%6,%7},{%8,%9},{%0,%1,%2,%3};"
        : "+f"(d[0]), "+f"(d[1]), "+f"(d[2]), "+f"(d[3])
        : "r"(a[0]), "r"(a[1]), "r"(a[2]), "r"(a[3]), "r"(b[0]), "r"(b[1]));
}
__device__ __forceinline__ void split2(float x0, float x1, u32& hi, u32& lo) {
    __nv_bfloat162 h = __floats2bfloat162_rn(x0, x1);
    float r0 = x0 - __bfloat162float(h.x);
    float r1 = x1 - __bfloat162float(h.y);
    __nv_bfloat162 l = __floats2bfloat162_rn(r0, r1);
    hi = *(u32*)&h;  lo = *(u32*)&l;
}
__device__ __forceinline__ void split1(float x, u16& hi, u16& lo) {
    __nv_bfloat16 h = __float2bfloat16(x);
    __nv_bfloat16 l = __float2bfloat16(x - __bfloat162float(h));
    hi = *(u16*)&h;  lo = *(u16*)&l;
}
__device__ __forceinline__ void split1h(float x, u16& hi, u16& lo) {
    __half h = __float2half_rn(x);
    __half l = __float2half_rn(x - __half2float(h));
    hi = *(u16*)&h;  lo = *(u16*)&l;
}
__device__ __forceinline__ void split2h(float x0, float x1, u32& hi, u32& lo) {
    __half2 h = __floats2half2_rn(x0, x1);
    float r0 = x0 - __half2float(__low2half(h));
    float r1 = x1 - __half2float(__high2half(h));
    __half2 l = __floats2half2_rn(r0, r1);
    hi = *(u32*)&h;  lo = *(u32*)&l;
}
__device__ __forceinline__ u32 pack_h2(float x0, float x1) {
    __half2 h = __floats2half2_rn(x0, x1);
    return *(u32*)&h;
}
__device__ __forceinline__ void cpasync16(u32 dst, const void* src) {
    asm volatile("cp.async.cg.shared.global [%0], [%1], 16;" :: "r"(dst), "l"(src));
}

// ---------- kernel 0a: W prep (fp16 split) ----------
__global__ void wprep_kernel(const float* __restrict__ Wq,
                             const float* __restrict__ Wk,
                             const float* __restrict__ Wv) {
    int idx = blockIdx.x*256 + threadIdx.x;
    int kk = idx & 31;
    int r  = idx >> 5;
    int n  = r % 192;
    int it = r / 192;
    int col = n & 63;
    const float* Wp = (n < 64) ? Wq : (n < 128) ? Wk : Wv;
    float w = Wp[(size_t)(it*32 + kk)*M_ + col];
    u16 hi, lo;
    split1h(w, hi, lo);
    g_Wh[idx] = hi;
    g_Wl[idx] = lo;
}

// ---------- kernel 0b: Wo prep (fp16 split pairs) ----------
__global__ void woprep_kernel(const float* __restrict__ Wo) {
    int idx = blockIdx.x*256 + threadIdx.x;
    int kp = idx & 31;
    int n  = (idx >> 5) & 127;
    int blk = idx >> 12;
    int ng = blk*128 + n;
    u32 hi, lo;
    split2h(Wo[(size_t)(2*kp)*D_ + ng], Wo[(size_t)(2*kp+1)*D_ + ng], hi, lo);
    g_WoH[idx] = hi;
    g_WoL[idx] = lo;
}

// SMEM layout for qkv (fp16 X single buffer + fp16 W hi/lo, double-buffered)
#define RS 80
#define CRS 144
#define XHo(b)  ((b)*5120)
#define WHo(b)  (10240 + (b)*15360)
#define WLo(b)  (40960 + (b)*15360)
// fused chunk-sum staging (reuses buffers 0..36864 after main loop)
#define FS_AH 0
#define FS_AL 9216
#define FS_BH 18432
#define FS_BL 27648
#define WGV_OFF 71680
#define GATE_OFF 75776
#define DPOW_OFF 76032
#define QKV_SMEM 76288

// ========== kernel 1: fused QKV + gate + chunk-sum (A^T), 2 CTAs/SM ========
__global__ void __launch_bounds__(256, 2) qkv_mma_kernel(
        const float* __restrict__ x,
        const float* __restrict__ Wg, const float* __restrict__ bg,
        const float* __restrict__ dp) {
    extern __shared__ char smem[];
    u32 sb = smem_u32(smem);
    int t = threadIdx.x;
    int lane = t & 31, wid = t >> 5;
    int warp_m = wid >> 2, warp_n = wid & 3;
    int r0 = blockIdx.x * 64;

    *(float4*)(smem + WGV_OFF + t*16) = *(const float4*)(Wg + t*4);
    const float* wgs = (const float*)(smem + WGV_OFF);
    float* dpow = (float*)(smem + DPOW_OFF);
    if (t < 64) dpow[t] = powf(decay_val(dp), (float)t);

    int rowX = t >> 3;
    int c4   = t & 7;

    int wn[6], wc[6], wterm[6];
#pragma unroll
    for (int rr = 0; rr < 6; ++rr) {
        int idx = t + rr*256;
        wterm[rr] = (idx >= 768);
        int rem = idx - wterm[rr]*768;
        wn[rr] = rem >> 2;
        wc[rr] = rem & 3;
    }

    int laneA_row = lane & 15;
    int laneA_kb  = (lane >> 4) * 16;
    int laneB_n   = (lane & 7) + ((lane >> 4) << 3);
    int laneB_kb  = ((lane >> 3) & 1) * 16;

    float acc[2][6][4];
#pragma unroll
    for (int i = 0; i < 2; ++i)
#pragma unroll
        for (int j = 0; j < 6; ++j)
#pragma unroll
            for (int k = 0; k < 4; ++k) acc[i][j][k] = 0.f;
    float gacc[2] = {0.f, 0.f};

    __syncthreads();

    float4 xr0 = *(const float4*)(x + (size_t)(r0 + rowX)*D_ + c4*4);
    float4 xr1 = *(const float4*)(x + (size_t)(r0 + rowX + 32)*D_ + c4*4);
#pragma unroll
    for (int rr = 0; rr < 6; ++rr) {
        u32 dst = sb + (wterm[rr] ? WLo(0) : WHo(0)) + wn[rr]*RS + wc[rr]*16;
        const u16* src = (wterm[rr] ? g_Wl : g_Wh) + ((0*192 + wn[rr])*32 + wc[rr]*8);
        cpasync16(dst, src);
    }
    asm volatile("cp.async.commit_group;" ::: "memory");

#pragma unroll 1
    for (int it = 0; it < 32; ++it) {
        int buf = it & 1;
        int k0 = it * 32;
        {
            const float* wg4 = wgs + k0 + c4*4;
            gacc[0] += xr0.x*wg4[0] + xr0.y*wg4[1] + xr0.z*wg4[2] + xr0.w*wg4[3];
            gacc[1] += xr1.x*wg4[0] + xr1.y*wg4[1] + xr1.z*wg4[2] + xr1.w*wg4[3];
            u32 a0 = pack_h2(xr0.x, xr0.y), a1 = pack_h2(xr0.z, xr0.w);
            *(u64*)(smem + XHo(buf) + rowX*RS + c4*8) = ((u64)a1 << 32) | a0;
            a0 = pack_h2(xr1.x, xr1.y);  a1 = pack_h2(xr1.z, xr1.w);
            *(u64*)(smem + XHo(buf) + (rowX+32)*RS + c4*8) = ((u64)a1 << 32) | a0;
        }
        asm volatile("cp.async.wait_group 0;" ::: "memory");
        __syncthreads();
        if (it < 31) {
            int k1 = k0 + 32;
            xr0 = *(const float4*)(x + (size_t)(r0 + rowX)*D_ + k1 + c4*4);
            xr1 = *(const float4*)(x + (size_t)(r0 + rowX + 32)*D_ + k1 + c4*4);
#pragma unroll
            for (int rr = 0; rr < 6; ++rr) {
                u32 dst = sb + (wterm[rr] ? WLo(buf^1) : WHo(buf^1)) + wn[rr]*RS + wc[rr]*16;
                const u16* src = (wterm[rr] ? g_Wl : g_Wh)
                               + (((it+1)*192 + wn[rr])*32 + wc[rr]*8);
                cpasync16(dst, src);
            }
            asm volatile("cp.async.commit_group;" ::: "memory");
        }
#pragma unroll
        for (int ko = 0; ko < 2; ++ko) {
            int kb = ko*32;
            u32 Ah[2][4], Bb[6][2];
#pragma unroll
            for (int mt = 0; mt < 2; ++mt) {
                u32 aoff = (u32)((warp_m*32 + mt*16 + laneA_row)*RS + kb + laneA_kb);
                ldsm4(Ah[mt][0], Ah[mt][1], Ah[mt][2], Ah[mt][3], sb + XHo(buf) + aoff);
            }
#pragma unroll
            for (int np = 0; np < 3; ++np) {
                u32 boff = (u32)((warp_n*48 + np*16 + laneB_n)*RS + kb + laneB_kb);
                ldsm4(Bb[2*np][0], Bb[2*np][1], Bb[2*np+1][0], Bb[2*np+1][1],
                      sb + WHo(buf) + boff);
            }
#pragma unroll
            for (int mt = 0; mt < 2; ++mt)
#pragma unroll
                for (int nt = 0; nt < 6; ++nt) mma_f16(acc[mt][nt], Ah[mt], Bb[nt]);
#pragma unroll
            for (int np = 0; np < 3; ++np) {
                u32 boff = (u32)((warp_n*48 + np*16 + laneB_n)*RS + kb + laneB_kb);
                ldsm4(Bb[2*np][0], Bb[2*np][1], Bb[2*np+1][0], Bb[2*np+1][1],
                      sb + WLo(buf) + boff);
            }
#pragma unroll
            for (int mt = 0; mt < 2; ++mt)
#pragma unroll
                for (int nt = 0; nt < 6; ++nt) mma_f16(acc[mt][nt], Ah[mt], Bb[nt]);
        }
    }

    // ---- gates ----
#pragma unroll
    for (int off = 4; off; off >>= 1)
#pragma unroll
        for (int rep = 0; rep < 2; ++rep)
            gacc[rep] += __shfl_xor_sync(0xffffffffu, gacc[rep], off);
    if ((t & 7) == 0) {
        float bgv = bg[0];
        ((float*)(smem + GATE_OFF))[rowX]      = 1.0f/(1.0f + expf(-(gacc[0] + bgv)));
        ((float*)(smem + GATE_OFF))[rowX + 32] = 1.0f/(1.0f + expf(-(gacc[1] + bgv)));
    }
    __syncthreads();   // gates ready; main-loop smem reads done -> safe to reuse
    const float* gate = (const float*)(smem + GATE_OFF);

    // ---- epilogue: global writes + fused chunk-sum staging ----
    int g8 = lane >> 2, t2 = lane & 3;
#pragma unroll
    for (int mt = 0; mt < 2; ++mt) {
        int rl0 = warp_m*32 + mt*16 + g8;
        float w0 = dpow[63 - rl0], w1 = dpow[63 - (rl0 + 8)];
#pragma unroll
        for (int nt = 0; nt < 6; ++nt) {
            int col = warp_n*48 + nt*8 + t2*2;
            int proj = col >> 6, pair = (col & 63) >> 1;
            int lc = col & 63;
            u32* OutH = (proj == 0) ? g_QH : (proj == 1) ? g_KH : g_VH;
            u32* OutL = (proj == 0) ? g_QL : (proj == 1) ? g_QL : g_VL;
            OutL = (proj == 0) ? g_QL : (proj == 1) ? g_KL : g_VL;
            float ga = (proj == 0) ? 1.0f : gate[rl0];
            float gb = (proj == 0) ? 1.0f : gate[rl0 + 8];
            float v0 = acc[mt][nt][0]*ga, v1 = acc[mt][nt][1]*ga;
            float v2 = acc[mt][nt][2]*gb, v3 = acc[mt][nt][3]*gb;
            u32 hi, lo;
            split2(v0, v1, hi, lo);
            OutH[(size_t)(r0 + rl0)*32 + pair] = hi;
            OutL[(size_t)(r0 + rl0)*32 + pair] = lo;
            split2(v2, v3, hi, lo);
            OutH[(size_t)(r0 + rl0 + 8)*32 + pair] = hi;
            OutL[(size_t)(r0 + rl0 + 8)*32 + pair] = lo;
            if (proj == 1) {        // GKw^T -> B operand (decay-weighted)
                u16 h16, l16;
                split1(v0*w0, h16, l16);
                *(u16*)(smem + FS_BH + lc*CRS + rl0*2) = h16;
                *(u16*)(smem + FS_BL + lc*CRS + rl0*2) = l16;
                split1(v1*w0, h16, l16);
                *(u16*)(smem + FS_BH + (lc+1)*CRS + rl0*2) = h16;
                *(u16*)(smem + FS_BL + (lc+1)*CRS + rl0*2) = l16;
                split1(v2*w1, h16, l16);
                *(u16*)(smem + FS_BH + lc*CRS + (rl0+8)*2) = h16;
                *(u16*)(smem + FS_BL + lc*CRS + (rl0+8)*2) = l16;
                split1(v3*w1, h16, l16);
                *(u16*)(smem + FS_BH + (lc+1)*CRS + (rl0+8)*2) = h16;
                *(u16*)(smem + FS_BL + (lc+1)*CRS + (rl0+8)*2) = l16;
            } else if (proj == 2) { // GV^T -> A operand
                u16 h16, l16;
                split1(v0, h16, l16);
                *(u16*)(smem + FS_AH + lc*CRS + rl0*2) = h16;
                *(u16*)(smem + FS_AL + lc*CRS + rl0*2) = l16;
                split1(v1, h16, l16);
                *(u16*)(smem + FS_AH + (lc+1)*CRS + rl0*2) = h16;
                *(u16*)(smem + FS_AL + (lc+1)*CRS + rl0*2) = l16;
                split1(v2, h16, l16);
                *(u16*)(smem + FS_AH + lc*CRS + (rl0+8)*2) = h16;
                *(u16*)(smem + FS_AL + lc*CRS + (rl0+8)*2) = l16;
                split1(v3, h16, l16);
                *(u16*)(smem + FS_AH + (lc+1)*CRS + (rl0+8)*2) = h16;
                *(u16*)(smem + FS_AL + (lc+1)*CRS + (rl0+8)*2) = l16;
            }
        }
    }
    __syncthreads();

    // ---- fused chunk-sum MMA: A^T = GV^T @ GKw (bf16 3-term) ----
    {
        int cwm = wid >> 1, cwn = wid & 1;
        float cacc[4][4];
#pragma unroll
        for (int j = 0; j < 4; ++j)
#pragma unroll
            for (int k = 0; k < 4; ++k) cacc[j][k] = 0.f;
#pragma unroll
        for (int ko = 0; ko < 4; ++ko) {
            int kb = ko*32;
            u32 Ah[4], Al[4], Bb[4][2];
            u32 aoff = (u32)((cwm*16 + laneA_row)*CRS + kb + laneA_kb);
            ldsm4(Ah[0], Ah[1], Ah[2], Ah[3], sb + FS_AH + aoff);
            ldsm4(Al[0], Al[1], Al[2], Al[3], sb + FS_AL + aoff);
#pragma unroll
            for (int np = 0; np < 2; ++np) {
                u32 boff = (u32)((cwn*32 + np*16 + laneB_n)*CRS + kb + laneB_kb);
                ldsm4(Bb[2*np][0], Bb[2*np][1], Bb[2*np+1][0], Bb[2*np+1][1],
                      sb + FS_BH + boff);
            }
#pragma unroll
            for (int nt = 0; nt < 4; ++nt) mma_bf16(cacc[nt], Ah, Bb[nt]);
#pragma unroll
            for (int nt = 0; nt < 4; ++nt) mma_bf16(cacc[nt], Al, Bb[nt]);
#pragma unroll
            for (int np = 0; np < 2; ++np) {
                u32 boff = (u32)((cwn*32 + np*16 + laneB_n)*CRS + kb + laneB_kb);
                ldsm4(Bb[2*np][0], Bb[2*np][1], Bb[2*np+1][0], Bb[2*np+1][1],
                      sb + FS_BL + boff);
            }
#pragma unroll
            for (int nt = 0; nt < 4; ++nt) mma_bf16(cacc[nt], Ah, Bb[nt]);
        }
        size_t ab = (size_t)blockIdx.x * (M_*M_);
#pragma unroll
        for (int nt = 0; nt < 4; ++nt) {
            int j = cwn*32 + nt*8 + t2*2;
            int i0 = cwm*16 + g8;
            *(float2*)(g_A + ab + (size_t)i0*M_ + j)     = make_float2(cacc[nt][0], cacc[nt][1]);
            *(float2*)(g_A + ab + (size_t)(i0+8)*M_ + j) = make_float2(cacc[nt][2], cacc[nt][3]);
        }
    }
}

// --------- kernel 4: inter-chunk scan (transposed; MLP-8) ----------
__global__ void chunk_scan_kernel(const float* __restrict__ dp,
                                  float* __restrict__ sfinal) {
    int gid = blockIdx.x * blockDim.x + threadIdx.x;
    int b = gid >> 12;
    int e = gid & 4095;
    float d  = decay_val(dp);
    float dT = powf(d, 64.0f);
    float S = 0.f;
#pragma unroll 1
    for (int c0 = 0; c0 < C_; c0 += 8) {
        float a[8];
#pragma unroll
        for (int j = 0; j < 8; ++j)
            a[j] = g_A[((size_t)(b*C_ + c0 + j) << 12) + e];
#pragma unroll
        for (int j = 0; j < 8; ++j) {
            g_Spre[((size_t)(b*C_ + c0 + j) << 12) + e] = S;
            S = dT*S + a[j];
        }
    }
    sfinal[((size_t)b << 12) + (e & 63)*64 + (e >> 6)] = S;
}

// --------- kernel 5: per-chunk outputs (bf16 3-term; O -> fp16) ------------
#define CO_QH 0
#define CO_QL 9216
#define CO_PH 18432
#define CO_PL 27648
#define CO_BH 36864
#define CO_BL 46080
#define CO_DP 55296
#define CO_SMEM 55808

__device__ __forceinline__ float bflo(u32 v) {
    u16 h = (u16)(v & 0xffff);
    return __bfloat162float(*(__nv_bfloat16*)&h);
}
__device__ __forceinline__ float bfhi(u32 v) {
    u16 h = (u16)(v >> 16);
    return __bfloat162float(*(__nv_bfloat16*)&h);
}

__global__ void __launch_bounds__(256) chunk_out_kernel(const float* __restrict__ dp) {
    extern __shared__ char smem[];
    u32 sb = smem_u32(smem);
    int b = blockIdx.y, c = blockIdx.x;
    int t = threadIdx.x, lane = t & 31, wid = t >> 5;
    int warp_m = wid >> 1, warp_n = wid & 1;
    float d = decay_val(dp);
    float* dpow = (float*)(smem + CO_DP);
    if (t < 65) dpow[t] = powf(d, (float)t);

    size_t grow = (size_t)b*L_ + (size_t)c*T_;
    size_t sbase = (size_t)(b*C_ + c) * (M_*M_);

#pragma unroll
    for (int rep = 0; rep < 2; ++rep) {
        int idx = t + rep*256;
        int row = idx >> 3, ch = idx & 7;
        u32 off = row*CRS + ch*16;
        cpasync16(sb + CO_QH + off, g_QH + (grow + row)*32 + ch*4);
        cpasync16(sb + CO_QL + off, g_QL + (grow + row)*32 + ch*4);
        cpasync16(sb + CO_BH + off, g_KH + (grow + row)*32 + ch*4);
        cpasync16(sb + CO_BL + off, g_KL + (grow + row)*32 + ch*4);
    }
    asm volatile("cp.async.commit_group;" ::: "memory");
    asm volatile("cp.async.wait_group 0;" ::: "memory");
    __syncthreads();

    int laneA_row = lane & 15;
    int laneA_kb  = (lane >> 4) * 16;
    int laneB_n   = (lane & 7) + ((lane >> 4) << 3);
    int laneB_kb  = ((lane >> 3) & 1) * 16;
    int g8 = lane >> 2, t2 = lane & 3;

    // phase 1: P = Q @ GK^T
    float pacc[4][4];
#pragma unroll
    for (int j = 0; j < 4; ++j)
#pragma unroll
        for (int k = 0; k < 4; ++k) pacc[j][k] = 0.f;
#pragma unroll
    for (int ko = 0; ko < 4; ++ko) {
        int kb = ko*32;
        u32 Ah[4], Al[4], Bb[4][2];
        u32 aoff = (u32)((warp_m*16 + laneA_row)*CRS + kb + laneA_kb);
        ldsm4(Ah[0], Ah[1], Ah[2], Ah[3], sb + CO_QH + aoff);
        ldsm4(Al[0], Al[1], Al[2], Al[3], sb + CO_QL + aoff);
#pragma unroll
        for (int np = 0; np < 2; ++np) {
            u32 boff = (u32)((warp_n*32 + np*16 + laneB_n)*CRS + kb + laneB_kb);
            ldsm4(Bb[2*np][0], Bb[2*np][1], Bb[2*np+1][0], Bb[2*np+1][1],
                  sb + CO_BH + boff);
        }
#pragma unroll
        for (int nt = 0; nt < 4; ++nt) mma_bf16(pacc[nt], Ah, Bb[nt]);
#pragma unroll
        for (int nt = 0; nt < 4; ++nt) mma_bf16(pacc[nt], Al, Bb[nt]);
#pragma unroll
        for (int np = 0; np < 2; ++np) {
            u32 boff = (u32)((warp_n*32 + np*16 + laneB_n)*CRS + kb + laneB_kb);
            ldsm4(Bb[2*np][0], Bb[2*np][1], Bb[2*np+1][0], Bb[2*np+1][1],
                  sb + CO_BL + boff);
        }
#pragma unroll
        for (int nt = 0; nt < 4; ++nt) mma_bf16(pacc[nt], Ah, Bb[nt]);
    }
#pragma unroll
    for (int nt = 0; nt < 4; ++nt) {
        int colb = warp_n*32 + nt*8 + t2*2;
        int ra = warp_m*16 + g8;
        float p0 = (colb   <= ra) ? pacc[nt][0]*dpow[ra - colb]     : 0.f;
        float p1 = (colb+1 <= ra) ? pacc[nt][1]*dpow[ra - colb - 1] : 0.f;
        int rb = ra + 8;
        float p2 = (colb   <= rb) ? pacc[nt][2]*dpow[rb - colb]     : 0.f;
        float p3 = (colb+1 <= rb) ? pacc[nt][3]*dpow[rb - colb - 1] : 0.f;
        u32 hi, lo;
        split2(p0, p1, hi, lo);
        *(u32*)(smem + CO_PH + ra*CRS + colb*2) = hi;
        *(u32*)(smem + CO_PL + ra*CRS + colb*2) = lo;
        split2(p2, p3, hi, lo);
        *(u32*)(smem + CO_PH + rb*CRS + colb*2) = hi;
        *(u32*)(smem + CO_PL + rb*CRS + colb*2) = lo;
    }
    __syncthreads();

    // stage Spre^T (natural fp32)
#pragma unroll
    for (int rep = 0; rep < 4; ++rep) {
        int idx = t + rep*256;
        int row = idx >> 4, c4 = idx & 15;
        float4 v = *(const float4*)(g_Spre + sbase + (size_t)row*M_ + c4*4);
        u32 h0,l0,h1,l1;
        split2(v.x, v.y, h0, l0);
        split2(v.z, v.w, h1, l1);
        int off = row*CRS + c4*8;
        *(u32*)(smem + CO_BH + off)   = h0;
        *(u32*)(smem + CO_BH + off+4) = h1;
        *(u32*)(smem + CO_BL + off)   = l0;
        *(u32*)(smem + CO_BL + off+4) = l1;
    }
    __syncthreads();

    // phase 2: acc = Q @ Spre
    float acc[4][4];
#pragma unroll
    for (int j = 0; j < 4; ++j)
#pragma unroll
        for (int k = 0; k < 4; ++k) acc[j][k] = 0.f;
#pragma unroll
    for (int ko = 0; ko < 4; ++ko) {
        int kb = ko*32;
        u32 Ah[4], Al[4], Bb[4][2];
        u32 aoff = (u32)((warp_m*16 + laneA_row)*CRS + kb + laneA_kb);
        ldsm4(Ah[0], Ah[1], Ah[2], Ah[3], sb + CO_QH + aoff);
        ldsm4(Al[0], Al[1], Al[2], Al[3], sb + CO_QL + aoff);
#pragma unroll
        for (int np = 0; np < 2; ++np) {
            u32 boff = (u32)((warp_n*32 + np*16 + laneB_n)*CRS + kb + laneB_kb);
            ldsm4(Bb[2*np][0], Bb[2*np][1], Bb[2*np+1][0], Bb[2*np+1][1],
                  sb + CO_BH + boff);
        }
#pragma unroll
        for (int nt = 0; nt < 4; ++nt) mma_bf16(acc[nt], Ah, Bb[nt]);
#pragma unroll
        for (int nt = 0; nt < 4; ++nt) mma_bf16(acc[nt], Al, Bb[nt]);
#pragma unroll
        for (int np = 0; np < 2; ++np) {
            u32 boff = (u32)((warp_n*32 + np*16 + laneB_n)*CRS + kb + laneB_kb);
            ldsm4(Bb[2*np][0], Bb[2*np][1], Bb[2*np+1][0], Bb[2*np+1][1],
                  sb + CO_BL + boff);
        }
#pragma unroll
        for (int nt = 0; nt < 4; ++nt) mma_bf16(acc[nt], Ah, Bb[nt]);
    }
    {
        int ra = warp_m*16 + g8;
        float sa = dpow[ra + 1], sbc = dpow[ra + 9];
#pragma unroll
        for (int nt = 0; nt < 4; ++nt) {
            acc[nt][0] *= sa;  acc[nt][1] *= sa;
            acc[nt][2] *= sbc; acc[nt][3] *= sbc;
        }
    }
    __syncthreads();

    // stage GV^T from pre-split pairs
#pragma unroll
    for (int rep = 0; rep < 8; ++rep) {
        int idx = t + rep*256;
        int s = idx >> 5, p = idx & 31;
        u32 vh = g_VH[(grow+s)*32 + p], vl = g_VL[(grow+s)*32 + p];
        *(u16*)(smem + CO_BH + (2*p)*CRS   + s*2) = (u16)(vh & 0xffff);
        *(u16*)(smem + CO_BH + (2*p+1)*CRS + s*2) = (u16)(vh >> 16);
        *(u16*)(smem + CO_BL + (2*p)*CRS   + s*2) = (u16)(vl & 0xffff);
        *(u16*)(smem + CO_BL + (2*p+1)*CRS + s*2) = (u16)(vl >> 16);
    }
    __syncthreads();

    // phase 3: acc += P @ GV
#pragma unroll
    for (int ko = 0; ko < 4; ++ko) {
        int kb = ko*32;
        u32 Ah[4], Al[4], Bb[4][2];
        u32 aoff = (u32)((warp_m*16 + laneA_row)*CRS + kb + laneA_kb);
        ldsm4(Ah[0], Ah[1], Ah[2], Ah[3], sb + CO_PH + aoff);
        ldsm4(Al[0], Al[1], Al[2], Al[3], sb + CO_PL + aoff);
#pragma unroll
        for (int np = 0; np < 2; ++np) {
            u32 boff = (u32)((warp_n*32 + np*16 + laneB_n)*CRS + kb + laneB_kb);
            ldsm4(Bb[2*np][0], Bb[2*np][1], Bb[2*np+1][0], Bb[2*np+1][1],
                  sb + CO_BH + boff);
        }
#pragma unroll
        for (int nt = 0; nt < 4; ++nt) mma_bf16(acc[nt], Ah, Bb[nt]);
#pragma unroll
        for (int nt = 0; nt < 4; ++nt) mma_bf16(acc[nt], Al, Bb[nt]);
#pragma unroll
        for (int np = 0; np < 2; ++np) {
            u32 boff = (u32)((warp_n*32 + np*16 + laneB_n)*CRS + kb + laneB_kb);
            ldsm4(Bb[2*np][0], Bb[2*np][1], Bb[2*np+1][0], Bb[2*np+1][1],
                  sb + CO_BL + boff);
        }
#pragma unroll
        for (int nt = 0; nt < 4; ++nt) mma_bf16(acc[nt], Ah, Bb[nt]);
    }

    // ---- write O as fp16 pairs ----
#pragma unroll
    for (int nt = 0; nt < 4; ++nt) {
        int j = warp_n*32 + nt*8 + t2*2;
        int pair = j >> 1;
        int i0 = warp_m*16 + g8;
        g_OHf[(grow + i0)*32 + pair]     = pack_h2(acc[nt][0], acc[nt][1]);
        g_OHf[(grow + i0 + 8)*32 + pair] = pack_h2(acc[nt][2], acc[nt][3]);
    }
}

// ---------- kernel 6: y = O @ Wo + bo (fp16 2-term) ----------
#define OH_OFF 0
#define WHO_OFF 18432
#define WLO_OFF 36864
#define OUT_SMEM 55296
#define ORS 144

__global__ void __launch_bounds__(256, 2) out_mma_kernel(
        const float* __restrict__ bo, float* __restrict__ y) {
    extern __shared__ char smem[];
    u32 sb = smem_u32(smem);
    int t = threadIdx.x;
    int lane = t & 31, wid = t >> 5;
    int warp_m = wid >> 1, warp_n = wid & 1;
    int r0 = blockIdx.x * 128;
    int n0 = blockIdx.y * 128;
    int blk = blockIdx.y;

#pragma unroll
    for (int p = 0; p < 4; ++p) {
        int idx = t + p*256;
        int row = idx >> 3, ch = idx & 7;
        cpasync16(sb + WHO_OFF + row*ORS + ch*16, g_WoH + ((blk*128 + row)*32 + ch*4));
        cpasync16(sb + WLO_OFF + row*ORS + ch*16, g_WoL + ((blk*128 + row)*32 + ch*4));
        cpasync16(sb + OH_OFF + row*ORS + ch*16, g_OHf + ((size_t)(r0 + row)*32 + ch*4));
    }
    asm volatile("cp.async.commit_group;" ::: "memory");
    asm volatile("cp.async.wait_group 0;" ::: "memory");
    __syncthreads();

    int laneA_row = lane & 15;
    int laneA_kb  = (lane >> 4) * 16;
    int laneB_n   = (lane & 7) + ((lane >> 4) << 3);
    int laneB_kb  = ((lane >> 3) & 1) * 16;

    float acc[2][8][4];
#pragma unroll
    for (int i = 0; i < 2; ++i)
#pragma unroll
        for (int j = 0; j < 8; ++j)
#pragma unroll
            for (int k = 0; k < 4; ++k) acc[i][j][k] = 0.f;

#pragma unroll
    for (int ko = 0; ko < 4; ++ko) {
        int kb = ko*32;
        u32 Ah[2][4], Bb[8][2];
#pragma unroll
        for (int mt = 0; mt < 2; ++mt) {
            u32 aoff = (u32)((warp_m*32 + mt*16 + laneA_row)*ORS + kb + laneA_kb);
            ldsm4(Ah[mt][0], Ah[mt][1], Ah[mt][2], Ah[mt][3], sb + OH_OFF + aoff);
        }
#pragma unroll
        for (int np = 0; np < 4; ++np) {
            u32 boff = (u32)((warp_n*64 + np*16 + laneB_n)*ORS + kb + laneB_kb);
            ldsm4(Bb[2*np][0], Bb[2*np][1], Bb[2*np+1][0], Bb[2*np+1][1],
                  sb + WHO_OFF + boff);
        }
#pragma unroll
        for (int mt = 0; mt < 2; ++mt)
#pragma unroll
            for (int nt = 0; nt < 8; ++nt) mma_f16(acc[mt][nt], Ah[mt], Bb[nt]);
#pragma unroll
        for (int np = 0; np < 4; ++np) {
            u32 boff = (u32)((warp_n*64 + np*16 + laneB_n)*ORS + kb + laneB_kb);
            ldsm4(Bb[2*np][0], Bb[2*np][1], Bb[2*np+1][0], Bb[2*np+1][1],
                  sb + WLO_OFF + boff);
        }
#pragma unroll
        for (int mt = 0; mt < 2; ++mt)
#pragma unroll
            for (int nt = 0; nt < 8; ++nt) mma_f16(acc[mt][nt], Ah[mt], Bb[nt]);
    }

    int g8 = lane >> 2, t2 = lane & 3;
#pragma unroll
    for (int mt = 0; mt < 2; ++mt) {
        int row = r0 + warp_m*32 + mt*16 + g8;
#pragma unroll
        for (int nt = 0; nt < 8; ++nt) {
            int col = n0 + warp_n*64 + nt*8 + t2*2;
            float2 bias = *(const float2*)(bo + col);
            *(float2*)(y + (size_t)row*D_ + col) =
                make_float2(acc[mt][nt][0] + bias.x, acc[mt][nt][1] + bias.y);
            *(float2*)(y + (size_t)(row + 8)*D_ + col) =
                make_float2(acc[mt][nt][2] + bias.x, acc[mt][nt][3] + bias.y);
        }
    }
}

// ---------------- launcher ----------------
extern "C" void kernel_launch(void* const* d_in, const int* in_sizes, int n_in,
                              void* d_out, int out_size) {
    const float* x  = (const float*)d_in[0];
    const float* Wq = (const float*)d_in[1];
    const float* Wk = (const float*)d_in[2];
    const float* Wv = (const float*)d_in[3];
    const float* Wo = (const float*)d_in[4];
    const float* bo = (const float*)d_in[5];
    const float* Wg = (const float*)d_in[6];
    const float* bg = (const float*)d_in[7];
    const float* dp = (const float*)d_in[8];
    float* y      = (float*)d_out;
    float* sfinal = y + (size_t)BL_ * D_;

    cudaFuncSetAttribute(qkv_mma_kernel,
                         cudaFuncAttributeMaxDynamicSharedMemorySize, QKV_SMEM);
    cudaFuncSetAttribute(out_mma_kernel,
                         cudaFuncAttributeMaxDynamicSharedMemorySize, OUT_SMEM);
    cudaFuncSetAttribute(chunk_out_kernel,
                         cudaFuncAttributeMaxDynamicSharedMemorySize, CO_SMEM);

    wprep_kernel     <<<768, 256>>>(Wq, Wk, Wv);
    woprep_kernel    <<<128, 256>>>(Wo);
    qkv_mma_kernel   <<<BL_/64, 256, QKV_SMEM>>>(x, Wg, bg, dp);
    chunk_scan_kernel<<<(B_*M_*M_)/256, 256>>>(dp, sfinal);
    chunk_out_kernel <<<dim3(C_, B_), 256, CO_SMEM>>>(dp);
    out_mma_kernel   <<<dim3(BL_/128, D_/128), 256, OUT_SMEM>>>(bo, y);
}

// round 14
// speedup vs baseline: 1.2716x; 1.0380x over previous
#include <cuda_runtime.h>
#include <cuda_bf16.h>
#include <cuda_fp16.h>
#include <cstdint>
#include <math.h>

#define B_  8
#define L_  4096
#define D_  1024
#define M_  64
#define BL_ (B_*L_)
#define C_  64
#define T_  64

typedef unsigned long long u64;
typedef unsigned int u32;
typedef unsigned short u16;

// ---------------- scratch ----------------
__device__ u32   g_QH[BL_*32], g_QL[BL_*32];
__device__ u32   g_KH[BL_*32], g_KL[BL_*32];
__device__ u32   g_VH[BL_*32], g_VL[BL_*32];
__device__ u32   g_OHf[BL_*32];
__device__ float g_A   [B_*C_*M_*M_];          // A^T[j][i]
__device__ float g_Spre[B_*C_*M_*M_];          // Spre^T[j][m]
__device__ u16   g_Wh  [32*192*32];
__device__ u16   g_Wl  [32*192*32];
__device__ u32   g_WoH [8*128*32];
__device__ u32   g_WoL [8*128*32];

__device__ __forceinline__ float decay_val(const float* dp) {
    return 0.9f + 0.099f / (1.0f + expf(-dp[0]));
}

// ---- helpers ----
__device__ __forceinline__ u32 smem_u32(const void* p) {
    u32 a;
    asm("{ .reg .u64 t; cvta.to.shared.u64 t, %1; cvt.u32.u64 %0, t; }" : "=r"(a) : "l"(p));
    return a;
}
__device__ __forceinline__ void ldsm4(u32& r0, u32& r1, u32& r2, u32& r3, u32 a) {
    asm volatile("ldmatrix.sync.aligned.m8n8.x4.shared.b16 {%0,%1,%2,%3},[%4];"
                 : "=r"(r0), "=r"(r1), "=r"(r2), "=r"(r3) : "r"(a));
}
__device__ __forceinline__ void mma_bf16(float* d, const u32* a, const u32* b) {
    asm volatile(
        "mma.sync.aligned.m16n8k16.row.col.f32.bf16.bf16.f32 "
        "{%0,%1,%2,%3},{%4,%5,%6,%7},{%8,%9},{%0,%1,%2,%3};"
        : "+f"(d[0]), "+f"(d[1]), "+f"(d[2]), "+f"(d[3])
        : "r"(a[0]), "r"(a[1]), "r"(a[2]), "r"(a[3]), "r"(b[0]), "r"(b[1]));
}
__device__ __forceinline__ void mma_f16(float* d, const u32* a, const u32* b) {
    asm volatile(
        "mma.sync.aligned.m16n8k16.row.col.f32.f16.f16.f32 "
        "{%0,%1,%2,%3},{%4,%5,%6,%7},{%8,%9},{%0,%1,%2,%3};"
        : "+f"(d[0]), "+f"(d[1]), "+f"(d[2]), "+f"(d[3])
        : "r"(a[0]), "r"(a[1]), "r"(a[2]), "r"(a[3]), "r"(b[0]), "r"(b[1]));
}
__device__ __forceinline__ void split2(float x0, float x1, u32& hi, u32& lo) {
    __nv_bfloat162 h = __floats2bfloat162_rn(x0, x1);
    float r0 = x0 - __bfloat162float(h.x);
    float r1 = x1 - __bfloat162float(h.y);
    __nv_bfloat162 l = __floats2bfloat162_rn(r0, r1);
    hi = *(u32*)&h;  lo = *(u32*)&l;
}
__device__ __forceinline__ void split1(float x, u16& hi, u16& lo) {
    __nv_bfloat16 h = __float2bfloat16(x);
    __nv_bfloat16 l = __float2bfloat16(x - __bfloat162float(h));
    hi = *(u16*)&h;  lo = *(u16*)&l;
}
__device__ __forceinline__ void split1h(float x, u16& hi, u16& lo) {
    __half h = __float2half_rn(x);
    __half l = __float2half_rn(x - __half2float(h));
    hi = *(u16*)&h;  lo = *(u16*)&l;
}
__device__ __forceinline__ void split2h(float x0, float x1, u32& hi, u32& lo) {
    __half2 h = __floats2half2_rn(x0, x1);
    float r0 = x0 - __half2float(__low2half(h));
    float r1 = x1 - __half2float(__high2half(h));
    __half2 l = __floats2half2_rn(r0, r1);
    hi = *(u32*)&h;  lo = *(u32*)&l;
}
__device__ __forceinline__ u32 pack_h2(float x0, float x1) {
    __half2 h = __floats2half2_rn(x0, x1);
    return *(u32*)&h;
}
__device__ __forceinline__ void cpasync16(u32 dst, const void* src) {
    asm volatile("cp.async.cg.shared.global [%0], [%1], 16;" :: "r"(dst), "l"(src));
}

// ---------- kernel 0: fused W + Wo prep (fp16 splits) ----------
__global__ void prep_kernel(const float* __restrict__ Wq,
                            const float* __restrict__ Wk,
                            const float* __restrict__ Wv,
                            const float* __restrict__ Wo) {
    int idx = blockIdx.x*256 + threadIdx.x;
    if (idx < 196608) {
        int kk = idx & 31;
        int r  = idx >> 5;
        int n  = r % 192;
        int it = r / 192;
        int col = n & 63;
        const float* Wp = (n < 64) ? Wq : (n < 128) ? Wk : Wv;
        float w = Wp[(size_t)(it*32 + kk)*M_ + col];
        u16 hi, lo;
        split1h(w, hi, lo);
        g_Wh[idx] = hi;
        g_Wl[idx] = lo;
    } else {
        int i2 = idx - 196608;          // 0..32767
        int kp = i2 & 31;
        int n  = (i2 >> 5) & 127;
        int blk = i2 >> 12;
        int ng = blk*128 + n;
        u32 hi, lo;
        split2h(Wo[(size_t)(2*kp)*D_ + ng], Wo[(size_t)(2*kp+1)*D_ + ng], hi, lo);
        g_WoH[i2] = hi;
        g_WoL[i2] = lo;
    }
}

// SMEM layout for qkv
#define RS 80
#define CRS 144
#define XHo(b)  ((b)*5120)
#define WHo(b)  (10240 + (b)*15360)
#define WLo(b)  (40960 + (b)*15360)
#define FS_AH 0
#define FS_AL 9216
#define FS_BH 18432
#define FS_BL 27648
#define WGV_OFF 71680
#define GATE_OFF 75776
#define DPOW_OFF 76032
#define QKV_SMEM 76288

// ========== kernel 1: fused QKV + gate + chunk-sum (A^T), 2 CTAs/SM ========
__global__ void __launch_bounds__(256, 2) qkv_mma_kernel(
        const float* __restrict__ x,
        const float* __restrict__ Wg, const float* __restrict__ bg,
        const float* __restrict__ dp) {
    extern __shared__ char smem[];
    u32 sb = smem_u32(smem);
    int t = threadIdx.x;
    int lane = t & 31, wid = t >> 5;
    int warp_m = wid >> 2, warp_n = wid & 3;
    int r0 = blockIdx.x * 64;

    *(float4*)(smem + WGV_OFF + t*16) = *(const float4*)(Wg + t*4);
    const float* wgs = (const float*)(smem + WGV_OFF);
    float* dpow = (float*)(smem + DPOW_OFF);
    if (t < 64) dpow[t] = powf(decay_val(dp), (float)t);

    int rowX = t >> 3;
    int c4   = t & 7;

    int wn[6], wc[6], wterm[6];
#pragma unroll
    for (int rr = 0; rr < 6; ++rr) {
        int idx = t + rr*256;
        wterm[rr] = (idx >= 768);
        int rem = idx - wterm[rr]*768;
        wn[rr] = rem >> 2;
        wc[rr] = rem & 3;
    }

    int laneA_row = lane & 15;
    int laneA_kb  = (lane >> 4) * 16;
    int laneB_n   = (lane & 7) + ((lane >> 4) << 3);
    int laneB_kb  = ((lane >> 3) & 1) * 16;

    float acc[2][6][4];
#pragma unroll
    for (int i = 0; i < 2; ++i)
#pragma unroll
        for (int j = 0; j < 6; ++j)
#pragma unroll
            for (int k = 0; k < 4; ++k) acc[i][j][k] = 0.f;
    float gacc[2] = {0.f, 0.f};

    __syncthreads();

    float4 xr0 = __ldcs((const float4*)(x + (size_t)(r0 + rowX)*D_ + c4*4));
    float4 xr1 = __ldcs((const float4*)(x + (size_t)(r0 + rowX + 32)*D_ + c4*4));
#pragma unroll
    for (int rr = 0; rr < 6; ++rr) {
        u32 dst = sb + (wterm[rr] ? WLo(0) : WHo(0)) + wn[rr]*RS + wc[rr]*16;
        const u16* src = (wterm[rr] ? g_Wl : g_Wh) + ((0*192 + wn[rr])*32 + wc[rr]*8);
        cpasync16(dst, src);
    }
    asm volatile("cp.async.commit_group;" ::: "memory");

#pragma unroll 1
    for (int it = 0; it < 32; ++it) {
        int buf = it & 1;
        int k0 = it * 32;
        {
            const float* wg4 = wgs + k0 + c4*4;
            gacc[0] += xr0.x*wg4[0] + xr0.y*wg4[1] + xr0.z*wg4[2] + xr0.w*wg4[3];
            gacc[1] += xr1.x*wg4[0] + xr1.y*wg4[1] + xr1.z*wg4[2] + xr1.w*wg4[3];
            u32 a0 = pack_h2(xr0.x, xr0.y), a1 = pack_h2(xr0.z, xr0.w);
            *(u64*)(smem + XHo(buf) + rowX*RS + c4*8) = ((u64)a1 << 32) | a0;
            a0 = pack_h2(xr1.x, xr1.y);  a1 = pack_h2(xr1.z, xr1.w);
            *(u64*)(smem + XHo(buf) + (rowX+32)*RS + c4*8) = ((u64)a1 << 32) | a0;
        }
        asm volatile("cp.async.wait_group 0;" ::: "memory");
        __syncthreads();
        if (it < 31) {
            int k1 = k0 + 32;
            xr0 = __ldcs((const float4*)(x + (size_t)(r0 + rowX)*D_ + k1 + c4*4));
            xr1 = __ldcs((const float4*)(x + (size_t)(r0 + rowX + 32)*D_ + k1 + c4*4));
#pragma unroll
            for (int rr = 0; rr < 6; ++rr) {
                u32 dst = sb + (wterm[rr] ? WLo(buf^1) : WHo(buf^1)) + wn[rr]*RS + wc[rr]*16;
                const u16* src = (wterm[rr] ? g_Wl : g_Wh)
                               + (((it+1)*192 + wn[rr])*32 + wc[rr]*8);
                cpasync16(dst, src);
            }
            asm volatile("cp.async.commit_group;" ::: "memory");
        }
#pragma unroll
        for (int ko = 0; ko < 2; ++ko) {
            int kb = ko*32;
            u32 Ah[2][4], Bb[6][2];
#pragma unroll
            for (int mt = 0; mt < 2; ++mt) {
                u32 aoff = (u32)((warp_m*32 + mt*16 + laneA_row)*RS + kb + laneA_kb);
                ldsm4(Ah[mt][0], Ah[mt][1], Ah[mt][2], Ah[mt][3], sb + XHo(buf) + aoff);
            }
#pragma unroll
            for (int np = 0; np < 3; ++np) {
                u32 boff = (u32)((warp_n*48 + np*16 + laneB_n)*RS + kb + laneB_kb);
                ldsm4(Bb[2*np][0], Bb[2*np][1], Bb[2*np+1][0], Bb[2*np+1][1],
                      sb + WHo(buf) + boff);
            }
#pragma unroll
            for (int mt = 0; mt < 2; ++mt)
#pragma unroll
                for (int nt = 0; nt < 6; ++nt) mma_f16(acc[mt][nt], Ah[mt], Bb[nt]);
#pragma unroll
            for (int np = 0; np < 3; ++np) {
                u32 boff = (u32)((warp_n*48 + np*16 + laneB_n)*RS + kb + laneB_kb);
                ldsm4(Bb[2*np][0], Bb[2*np][1], Bb[2*np+1][0], Bb[2*np+1][1],
                      sb + WLo(buf) + boff);
            }
#pragma unroll
            for (int mt = 0; mt < 2; ++mt)
#pragma unroll
                for (int nt = 0; nt < 6; ++nt) mma_f16(acc[mt][nt], Ah[mt], Bb[nt]);
        }
    }

    // ---- gates ----
#pragma unroll
    for (int off = 4; off; off >>= 1)
#pragma unroll
        for (int rep = 0; rep < 2; ++rep)
            gacc[rep] += __shfl_xor_sync(0xffffffffu, gacc[rep], off);
    if ((t & 7) == 0) {
        float bgv = bg[0];
        ((float*)(smem + GATE_OFF))[rowX]      = 1.0f/(1.0f + expf(-(gacc[0] + bgv)));
        ((float*)(smem + GATE_OFF))[rowX + 32] = 1.0f/(1.0f + expf(-(gacc[1] + bgv)));
    }
    __syncthreads();
    const float* gate = (const float*)(smem + GATE_OFF);

    // ---- epilogue: global writes + fused chunk-sum staging ----
    int g8 = lane >> 2, t2 = lane & 3;
#pragma unroll
    for (int mt = 0; mt < 2; ++mt) {
        int rl0 = warp_m*32 + mt*16 + g8;
        float w0 = dpow[63 - rl0], w1 = dpow[63 - (rl0 + 8)];
#pragma unroll
        for (int nt = 0; nt < 6; ++nt) {
            int col = warp_n*48 + nt*8 + t2*2;
            int proj = col >> 6, pair = (col & 63) >> 1;
            int lc = col & 63;
            u32* OutH = (proj == 0) ? g_QH : (proj == 1) ? g_KH : g_VH;
            u32* OutL = (proj == 0) ? g_QL : (proj == 1) ? g_KL : g_VL;
            float ga = (proj == 0) ? 1.0f : gate[rl0];
            float gb = (proj == 0) ? 1.0f : gate[rl0 + 8];
            float v0 = acc[mt][nt][0]*ga, v1 = acc[mt][nt][1]*ga;
            float v2 = acc[mt][nt][2]*gb, v3 = acc[mt][nt][3]*gb;
            u32 hi, lo;
            split2(v0, v1, hi, lo);
            OutH[(size_t)(r0 + rl0)*32 + pair] = hi;
            OutL[(size_t)(r0 + rl0)*32 + pair] = lo;
            split2(v2, v3, hi, lo);
            OutH[(size_t)(r0 + rl0 + 8)*32 + pair] = hi;
            OutL[(size_t)(r0 + rl0 + 8)*32 + pair] = lo;
            if (proj == 1) {
                u16 h16, l16;
                split1(v0*w0, h16, l16);
                *(u16*)(smem + FS_BH + lc*CRS + rl0*2) = h16;
                *(u16*)(smem + FS_BL + lc*CRS + rl0*2) = l16;
                split1(v1*w0, h16, l16);
                *(u16*)(smem + FS_BH + (lc+1)*CRS + rl0*2) = h16;
                *(u16*)(smem + FS_BL + (lc+1)*CRS + rl0*2) = l16;
                split1(v2*w1, h16, l16);
                *(u16*)(smem + FS_BH + lc*CRS + (rl0+8)*2) = h16;
                *(u16*)(smem + FS_BL + lc*CRS + (rl0+8)*2) = l16;
                split1(v3*w1, h16, l16);
                *(u16*)(smem + FS_BH + (lc+1)*CRS + (rl0+8)*2) = h16;
                *(u16*)(smem + FS_BL + (lc+1)*CRS + (rl0+8)*2) = l16;
            } else if (proj == 2) {
                u16 h16, l16;
                split1(v0, h16, l16);
                *(u16*)(smem + FS_AH + lc*CRS + rl0*2) = h16;
                *(u16*)(smem + FS_AL + lc*CRS + rl0*2) = l16;
                split1(v1, h16, l16);
                *(u16*)(smem + FS_AH + (lc+1)*CRS + rl0*2) = h16;
                *(u16*)(smem + FS_AL + (lc+1)*CRS + rl0*2) = l16;
                split1(v2, h16, l16);
                *(u16*)(smem + FS_AH + lc*CRS + (rl0+8)*2) = h16;
                *(u16*)(smem + FS_AL + lc*CRS + (rl0+8)*2) = l16;
                split1(v3, h16, l16);
                *(u16*)(smem + FS_AH + (lc+1)*CRS + (rl0+8)*2) = h16;
                *(u16*)(smem + FS_AL + (lc+1)*CRS + (rl0+8)*2) = l16;
            }
        }
    }
    __syncthreads();

    // ---- fused chunk-sum MMA: A^T = GV^T @ GKw (bf16 3-term) ----
    {
        int cwm = wid >> 1, cwn = wid & 1;
        float cacc[4][4];
#pragma unroll
        for (int j = 0; j < 4; ++j)
#pragma unroll
            for (int k = 0; k < 4; ++k) cacc[j][k] = 0.f;
#pragma unroll
        for (int ko = 0; ko < 4; ++ko) {
            int kb = ko*32;
            u32 Ah[4], Al[4], Bb[4][2];
            u32 aoff = (u32)((cwm*16 + laneA_row)*CRS + kb + laneA_kb);
            ldsm4(Ah[0], Ah[1], Ah[2], Ah[3], sb + FS_AH + aoff);
            ldsm4(Al[0], Al[1], Al[2], Al[3], sb + FS_AL + aoff);
#pragma unroll
            for (int np = 0; np < 2; ++np) {
                u32 boff = (u32)((cwn*32 + np*16 + laneB_n)*CRS + kb + laneB_kb);
                ldsm4(Bb[2*np][0], Bb[2*np][1], Bb[2*np+1][0], Bb[2*np+1][1],
                      sb + FS_BH + boff);
            }
#pragma unroll
            for (int nt = 0; nt < 4; ++nt) mma_bf16(cacc[nt], Ah, Bb[nt]);
#pragma unroll
            for (int nt = 0; nt < 4; ++nt) mma_bf16(cacc[nt], Al, Bb[nt]);
#pragma unroll
            for (int np = 0; np < 2; ++np) {
                u32 boff = (u32)((cwn*32 + np*16 + laneB_n)*CRS + kb + laneB_kb);
                ldsm4(Bb[2*np][0], Bb[2*np][1], Bb[2*np+1][0], Bb[2*np+1][1],
                      sb + FS_BL + boff);
            }
#pragma unroll
            for (int nt = 0; nt < 4; ++nt) mma_bf16(cacc[nt], Ah, Bb[nt]);
        }
        size_t ab = (size_t)blockIdx.x * (M_*M_);
#pragma unroll
        for (int nt = 0; nt < 4; ++nt) {
            int j = cwn*32 + nt*8 + t2*2;
            int i0 = cwm*16 + g8;
            *(float2*)(g_A + ab + (size_t)i0*M_ + j)     = make_float2(cacc[nt][0], cacc[nt][1]);
            *(float2*)(g_A + ab + (size_t)(i0+8)*M_ + j) = make_float2(cacc[nt][2], cacc[nt][3]);
        }
    }
}

// --------- kernel 4: inter-chunk scan (float2/thread, MLP-8) ----------
__global__ void chunk_scan_kernel(const float* __restrict__ dp,
                                  float* __restrict__ sfinal) {
    int gid = blockIdx.x * blockDim.x + threadIdx.x;   // 16384 threads
    int b = gid >> 11;
    int e = (gid & 2047) * 2;
    float d  = decay_val(dp);
    float dT = powf(d, 64.0f);
    float2 S = make_float2(0.f, 0.f);
#pragma unroll 1
    for (int c0 = 0; c0 < C_; c0 += 8) {
        float2 a[8];
#pragma unroll
        for (int j = 0; j < 8; ++j)
            a[j] = *(const float2*)(g_A + ((size_t)(b*C_ + c0 + j) << 12) + e);
#pragma unroll
        for (int j = 0; j < 8; ++j) {
            *(float2*)(g_Spre + ((size_t)(b*C_ + c0 + j) << 12) + e) = S;
            S.x = dT*S.x + a[j].x;
            S.y = dT*S.y + a[j].y;
        }
    }
    __stcs(sfinal + ((size_t)b << 12) + (e & 63)*64 + (e >> 6), S.x);
    __stcs(sfinal + ((size_t)b << 12) + ((e+1) & 63)*64 + ((e+1) >> 6), S.y);
}

// --------- kernel 5: per-chunk outputs (bf16 3-term; O -> fp16) ------------
#define CO_QH 0
#define CO_QL 9216
#define CO_PH 18432
#define CO_PL 27648
#define CO_BH 36864
#define CO_BL 46080
#define CO_DP 55296
#define CO_SMEM 55808

__global__ void __launch_bounds__(256) chunk_out_kernel(const float* __restrict__ dp) {
    extern __shared__ char smem[];
    u32 sb = smem_u32(smem);
    int b = blockIdx.y, c = blockIdx.x;
    int t = threadIdx.x, lane = t & 31, wid = t >> 5;
    int warp_m = wid >> 1, warp_n = wid & 1;
    float d = decay_val(dp);
    float* dpow = (float*)(smem + CO_DP);
    if (t < 65) dpow[t] = powf(d, (float)t);

    size_t grow = (size_t)b*L_ + (size_t)c*T_;
    size_t sbase = (size_t)(b*C_ + c) * (M_*M_);

#pragma unroll
    for (int rep = 0; rep < 2; ++rep) {
        int idx = t + rep*256;
        int row = idx >> 3, ch = idx & 7;
        u32 off = row*CRS + ch*16;
        cpasync16(sb + CO_QH + off, g_QH + (grow + row)*32 + ch*4);
        cpasync16(sb + CO_QL + off, g_QL + (grow + row)*32 + ch*4);
        cpasync16(sb + CO_BH + off, g_KH + (grow + row)*32 + ch*4);
        cpasync16(sb + CO_BL + off, g_KL + (grow + row)*32 + ch*4);
    }
    asm volatile("cp.async.commit_group;" ::: "memory");
    asm volatile("cp.async.wait_group 0;" ::: "memory");
    __syncthreads();

    int laneA_row = lane & 15;
    int laneA_kb  = (lane >> 4) * 16;
    int laneB_n   = (lane & 7) + ((lane >> 4) << 3);
    int laneB_kb  = ((lane >> 3) & 1) * 16;
    int g8 = lane >> 2, t2 = lane & 3;

    // phase 1: P = Q @ GK^T
    float pacc[4][4];
#pragma unroll
    for (int j = 0; j < 4; ++j)
#pragma unroll
        for (int k = 0; k < 4; ++k) pacc[j][k] = 0.f;
#pragma unroll
    for (int ko = 0; ko < 4; ++ko) {
        int kb = ko*32;
        u32 Ah[4], Al[4], Bb[4][2];
        u32 aoff = (u32)((warp_m*16 + laneA_row)*CRS + kb + laneA_kb);
        ldsm4(Ah[0], Ah[1], Ah[2], Ah[3], sb + CO_QH + aoff);
        ldsm4(Al[0], Al[1], Al[2], Al[3], sb + CO_QL + aoff);
#pragma unroll
        for (int np = 0; np < 2; ++np) {
            u32 boff = (u32)((warp_n*32 + np*16 + laneB_n)*CRS + kb + laneB_kb);
            ldsm4(Bb[2*np][0], Bb[2*np][1], Bb[2*np+1][0], Bb[2*np+1][1],
                  sb + CO_BH + boff);
        }
#pragma unroll
        for (int nt = 0; nt < 4; ++nt) mma_bf16(pacc[nt], Ah, Bb[nt]);
#pragma unroll
        for (int nt = 0; nt < 4; ++nt) mma_bf16(pacc[nt], Al, Bb[nt]);
#pragma unroll
        for (int np = 0; np < 2; ++np) {
            u32 boff = (u32)((warp_n*32 + np*16 + laneB_n)*CRS + kb + laneB_kb);
            ldsm4(Bb[2*np][0], Bb[2*np][1], Bb[2*np+1][0], Bb[2*np+1][1],
                  sb + CO_BL + boff);
        }
#pragma unroll
        for (int nt = 0; nt < 4; ++nt) mma_bf16(pacc[nt], Ah, Bb[nt]);
    }
#pragma unroll
    for (int nt = 0; nt < 4; ++nt) {
        int colb = warp_n*32 + nt*8 + t2*2;
        int ra = warp_m*16 + g8;
        float p0 = (colb   <= ra) ? pacc[nt][0]*dpow[ra - colb]     : 0.f;
        float p1 = (colb+1 <= ra) ? pacc[nt][1]*dpow[ra - colb - 1] : 0.f;
        int rb = ra + 8;
        float p2 = (colb   <= rb) ? pacc[nt][2]*dpow[rb - colb]     : 0.f;
        float p3 = (colb+1 <= rb) ? pacc[nt][3]*dpow[rb - colb - 1] : 0.f;
        u32 hi, lo;
        split2(p0, p1, hi, lo);
        *(u32*)(smem + CO_PH + ra*CRS + colb*2) = hi;
        *(u32*)(smem + CO_PL + ra*CRS + colb*2) = lo;
        split2(p2, p3, hi, lo);
        *(u32*)(smem + CO_PH + rb*CRS + colb*2) = hi;
        *(u32*)(smem + CO_PL + rb*CRS + colb*2) = lo;
    }
    __syncthreads();

    // stage Spre^T (natural fp32)
#pragma unroll
    for (int rep = 0; rep < 4; ++rep) {
        int idx = t + rep*256;
        int row = idx >> 4, c4 = idx & 15;
        float4 v = *(const float4*)(g_Spre + sbase + (size_t)row*M_ + c4*4);
        u32 h0,l0,h1,l1;
        split2(v.x, v.y, h0, l0);
        split2(v.z, v.w, h1, l1);
        int off = row*CRS + c4*8;
        *(u32*)(smem + CO_BH + off)   = h0;
        *(u32*)(smem + CO_BH + off+4) = h1;
        *(u32*)(smem + CO_BL + off)   = l0;
        *(u32*)(smem + CO_BL + off+4) = l1;
    }
    __syncthreads();

    // phase 2: acc = Q @ Spre
    float acc[4][4];
#pragma unroll
    for (int j = 0; j < 4; ++j)
#pragma unroll
        for (int k = 0; k < 4; ++k) acc[j][k] = 0.f;
#pragma unroll
    for (int ko = 0; ko < 4; ++ko) {
        int kb = ko*32;
        u32 Ah[4], Al[4], Bb[4][2];
        u32 aoff = (u32)((warp_m*16 + laneA_row)*CRS + kb + laneA_kb);
        ldsm4(Ah[0], Ah[1], Ah[2], Ah[3], sb + CO_QH + aoff);
        ldsm4(Al[0], Al[1], Al[2], Al[3], sb + CO_QL + aoff);
#pragma unroll
        for (int np = 0; np < 2; ++np) {
            u32 boff = (u32)((warp_n*32 + np*16 + laneB_n)*CRS + kb + laneB_kb);
            ldsm4(Bb[2*np][0], Bb[2*np][1], Bb[2*np+1][0], Bb[2*np+1][1],
                  sb + CO_BH + boff);
        }
#pragma unroll
        for (int nt = 0; nt < 4; ++nt) mma_bf16(acc[nt], Ah, Bb[nt]);
#pragma unroll
        for (int nt = 0; nt < 4; ++nt) mma_bf16(acc[nt], Al, Bb[nt]);
#pragma unroll
        for (int np = 0; np < 2; ++np) {
            u32 boff = (u32)((warp_n*32 + np*16 + laneB_n)*CRS + kb + laneB_kb);
            ldsm4(Bb[2*np][0], Bb[2*np][1], Bb[2*np+1][0], Bb[2*np+1][1],
                  sb + CO_BL + boff);
        }
#pragma unroll
        for (int nt = 0; nt < 4; ++nt) mma_bf16(acc[nt], Ah, Bb[nt]);
    }
    {
        int ra = warp_m*16 + g8;
        float sa = dpow[ra + 1], sbc = dpow[ra + 9];
#pragma unroll
        for (int nt = 0; nt < 4; ++nt) {
            acc[nt][0] *= sa;  acc[nt][1] *= sa;
            acc[nt][2] *= sbc; acc[nt][3] *= sbc;
        }
    }
    __syncthreads();

    // stage GV^T from pre-split pairs
#pragma unroll
    for (int rep = 0; rep < 8; ++rep) {
        int idx = t + rep*256;
        int s = idx >> 5, p = idx & 31;
        u32 vh = g_VH[(grow+s)*32 + p], vl = g_VL[(grow+s)*32 + p];
        *(u16*)(smem + CO_BH + (2*p)*CRS   + s*2) = (u16)(vh & 0xffff);
        *(u16*)(smem + CO_BH + (2*p+1)*CRS + s*2) = (u16)(vh >> 16);
        *(u16*)(smem + CO_BL + (2*p)*CRS   + s*2) = (u16)(vl & 0xffff);
        *(u16*)(smem + CO_BL + (2*p+1)*CRS + s*2) = (u16)(vl >> 16);
    }
    __syncthreads();

    // phase 3: acc += P @ GV
#pragma unroll
    for (int ko = 0; ko < 4; ++ko) {
        int kb = ko*32;
        u32 Ah[4], Al[4], Bb[4][2];
        u32 aoff = (u32)((warp_m*16 + laneA_row)*CRS + kb + laneA_kb);
        ldsm4(Ah[0], Ah[1], Ah[2], Ah[3], sb + CO_PH + aoff);
        ldsm4(Al[0], Al[1], Al[2], Al[3], sb + CO_PL + aoff);
#pragma unroll
        for (int np = 0; np < 2; ++np) {
            u32 boff = (u32)((warp_n*32 + np*16 + laneB_n)*CRS + kb + laneB_kb);
            ldsm4(Bb[2*np][0], Bb[2*np][1], Bb[2*np+1][0], Bb[2*np+1][1],
                  sb + CO_BH + boff);
        }
#pragma unroll
        for (int nt = 0; nt < 4; ++nt) mma_bf16(acc[nt], Ah, Bb[nt]);
#pragma unroll
        for (int nt = 0; nt < 4; ++nt) mma_bf16(acc[nt], Al, Bb[nt]);
#pragma unroll
        for (int np = 0; np < 2; ++np) {
            u32 boff = (u32)((warp_n*32 + np*16 + laneB_n)*CRS + kb + laneB_kb);
            ldsm4(Bb[2*np][0], Bb[2*np][1], Bb[2*np+1][0], Bb[2*np+1][1],
                  sb + CO_BL + boff);
        }
#pragma unroll
        for (int nt = 0; nt < 4; ++nt) mma_bf16(acc[nt], Ah, Bb[nt]);
    }

    // ---- write O as fp16 pairs ----
#pragma unroll
    for (int nt = 0; nt < 4; ++nt) {
        int j = warp_n*32 + nt*8 + t2*2;
        int pair = j >> 1;
        int i0 = warp_m*16 + g8;
        g_OHf[(grow + i0)*32 + pair]     = pack_h2(acc[nt][0], acc[nt][1]);
        g_OHf[(grow + i0 + 8)*32 + pair] = pack_h2(acc[nt][2], acc[nt][3]);
    }
}

// ---------- kernel 6: y = O @ Wo + bo (fp16 2-term; streaming y) ----------
#define OH_OFF 0
#define WHO_OFF 18432
#define WLO_OFF 36864
#define OUT_SMEM 55296
#define ORS 144

__global__ void __launch_bounds__(256, 2) out_mma_kernel(
        const float* __restrict__ bo, float* __restrict__ y) {
    extern __shared__ char smem[];
    u32 sb = smem_u32(smem);
    int t = threadIdx.x;
    int lane = t & 31, wid = t >> 5;
    int warp_m = wid >> 1, warp_n = wid & 1;
    int r0 = blockIdx.x * 128;
    int n0 = blockIdx.y * 128;
    int blk = blockIdx.y;

#pragma unroll
    for (int p = 0; p < 4; ++p) {
        int idx = t + p*256;
        int row = idx >> 3, ch = idx & 7;
        cpasync16(sb + WHO_OFF + row*ORS + ch*16, g_WoH + ((blk*128 + row)*32 + ch*4));
        cpasync16(sb + WLO_OFF + row*ORS + ch*16, g_WoL + ((blk*128 + row)*32 + ch*4));
        cpasync16(sb + OH_OFF + row*ORS + ch*16, g_OHf + ((size_t)(r0 + row)*32 + ch*4));
    }
    asm volatile("cp.async.commit_group;" ::: "memory");
    asm volatile("cp.async.wait_group 0;" ::: "memory");
    __syncthreads();

    int laneA_row = lane & 15;
    int laneA_kb  = (lane >> 4) * 16;
    int laneB_n   = (lane & 7) + ((lane >> 4) << 3);
    int laneB_kb  = ((lane >> 3) & 1) * 16;

    float acc[2][8][4];
#pragma unroll
    for (int i = 0; i < 2; ++i)
#pragma unroll
        for (int j = 0; j < 8; ++j)
#pragma unroll
            for (int k = 0; k < 4; ++k) acc[i][j][k] = 0.f;

#pragma unroll
    for (int ko = 0; ko < 4; ++ko) {
        int kb = ko*32;
        u32 Ah[2][4], Bb[8][2];
#pragma unroll
        for (int mt = 0; mt < 2; ++mt) {
            u32 aoff = (u32)((warp_m*32 + mt*16 + laneA_row)*ORS + kb + laneA_kb);
            ldsm4(Ah[mt][0], Ah[mt][1], Ah[mt][2], Ah[mt][3], sb + OH_OFF + aoff);
        }
#pragma unroll
        for (int np = 0; np < 4; ++np) {
            u32 boff = (u32)((warp_n*64 + np*16 + laneB_n)*ORS + kb + laneB_kb);
            ldsm4(Bb[2*np][0], Bb[2*np][1], Bb[2*np+1][0], Bb[2*np+1][1],
                  sb + WHO_OFF + boff);
        }
#pragma unroll
        for (int mt = 0; mt < 2; ++mt)
#pragma unroll
            for (int nt = 0; nt < 8; ++nt) mma_f16(acc[mt][nt], Ah[mt], Bb[nt]);
#pragma unroll
        for (int np = 0; np < 4; ++np) {
            u32 boff = (u32)((warp_n*64 + np*16 + laneB_n)*ORS + kb + laneB_kb);
            ldsm4(Bb[2*np][0], Bb[2*np][1], Bb[2*np+1][0], Bb[2*np+1][1],
                  sb + WLO_OFF + boff);
        }
#pragma unroll
        for (int mt = 0; mt < 2; ++mt)
#pragma unroll
            for (int nt = 0; nt < 8; ++nt) mma_f16(acc[mt][nt], Ah[mt], Bb[nt]);
    }

    int g8 = lane >> 2, t2 = lane & 3;
#pragma unroll
    for (int mt = 0; mt < 2; ++mt) {
        int row = r0 + warp_m*32 + mt*16 + g8;
#pragma unroll
        for (int nt = 0; nt < 8; ++nt) {
            int col = n0 + warp_n*64 + nt*8 + t2*2;
            float2 bias = *(const float2*)(bo + col);
            __stcs((float2*)(y + (size_t)row*D_ + col),
                   make_float2(acc[mt][nt][0] + bias.x, acc[mt][nt][1] + bias.y));
            __stcs((float2*)(y + (size_t)(row + 8)*D_ + col),
                   make_float2(acc[mt][nt][2] + bias.x, acc[mt][nt][3] + bias.y));
        }
    }
}

// ---------------- launcher ----------------
extern "C" void kernel_launch(void* const* d_in, const int* in_sizes, int n_in,
                              void* d_out, int out_size) {
    const float* x  = (const float*)d_in[0];
    const float* Wq = (const float*)d_in[1];
    const float* Wk = (const float*)d_in[2];
    const float* Wv = (const float*)d_in[3];
    const float* Wo = (const float*)d_in[4];
    const float* bo = (const float*)d_in[5];
    const float* Wg = (const float*)d_in[6];
    const float* bg = (const float*)d_in[7];
    const float* dp = (const float*)d_in[8];
    float* y      = (float*)d_out;
    float* sfinal = y + (size_t)BL_ * D_;

    cudaFuncSetAttribute(qkv_mma_kernel,
                         cudaFuncAttributeMaxDynamicSharedMemorySize, QKV_SMEM);
    cudaFuncSetAttribute(out_mma_kernel,
                         cudaFuncAttributeMaxDynamicSharedMemorySize, OUT_SMEM);
    cudaFuncSetAttribute(chunk_out_kernel,
                         cudaFuncAttributeMaxDynamicSharedMemorySize, CO_SMEM);

    prep_kernel      <<<896, 256>>>(Wq, Wk, Wv, Wo);
    qkv_mma_kernel   <<<BL_/64, 256, QKV_SMEM>>>(x, Wg, bg, dp);
    chunk_scan_kernel<<<(B_*M_*M_)/512, 256>>>(dp, sfinal);
    chunk_out_kernel <<<dim3(C_, B_), 256, CO_SMEM>>>(dp);
    out_mma_kernel   <<<dim3(BL_/128, D_/128), 256, OUT_SMEM>>>(bo, y);
}

// round 15
// speedup vs baseline: 1.2873x; 1.0124x over previous
#include <cuda_runtime.h>
#include <cuda_bf16.h>
#include <cuda_fp16.h>
#include <cstdint>
#include <math.h>

#define B_  8
#define L_  4096
#define D_  1024
#define M_  64
#define BL_ (B_*L_)
#define C_  64
#define T_  64

typedef unsigned long long u64;
typedef unsigned int u32;
typedef unsigned short u16;

// ---------------- scratch (fp16-native intermediates) ----------------
__device__ u32   g_Qf[BL_*32];                 // Q single fp16 pairs
__device__ u32   g_KH[BL_*32], g_KL[BL_*32];   // gated K fp16 split pairs
__device__ u32   g_VH[BL_*32], g_VL[BL_*32];   // gated V fp16 split pairs
__device__ u32   g_OHf[BL_*32];                // O fp16 pairs
__device__ float g_A   [B_*C_*M_*M_];          // A^T[j][i]
__device__ float g_Spre[B_*C_*M_*M_];          // Spre^T[j][m]
__device__ u16   g_Wh  [32*192*32];
__device__ u16   g_Wl  [32*192*32];
__device__ u32   g_WoH [8*128*32];
__device__ u32   g_WoL [8*128*32];

__device__ __forceinline__ float decay_val(const float* dp) {
    return 0.9f + 0.099f / (1.0f + expf(-dp[0]));
}

// ---- helpers ----
__device__ __forceinline__ u32 smem_u32(const void* p) {
    u32 a;
    asm("{ .reg .u64 t; cvta.to.shared.u64 t, %1; cvt.u32.u64 %0, t; }" : "=r"(a) : "l"(p));
    return a;
}
__device__ __forceinline__ void ldsm4(u32& r0, u32& r1, u32& r2, u32& r3, u32 a) {
    asm volatile("ldmatrix.sync.aligned.m8n8.x4.shared.b16 {%0,%1,%2,%3},[%4];"
                 : "=r"(r0), "=r"(r1), "=r"(r2), "=r"(r3) : "r"(a));
}
__device__ __forceinline__ void mma_bf16(float* d, const u32* a, const u32* b) {
    asm volatile(
        "mma.sync.aligned.m16n8k16.row.col.f32.bf16.bf16.f32 "
        "{%0,%1,%2,%3},{%4,%5,%6,%7},{%8,%9},{%0,%1,%2,%3};"
        : "+f"(d[0]), "+f"(d[1]), "+f"(d[2]), "+f"(d[3])
        : "r"(a[0]), "r"(a[1]), "r"(a[2]), "r"(a[3]), "r"(b[0]), "r"(b[1]));
}
__device__ __forceinline__ void mma_f16(float* d, const u32* a, const u32* b) {
    asm volatile(
        "mma.sync.aligned.m16n8k16.row.col.f32.f16.f16.f32 "
        "{%0,%1,%2,%3},{%4,%5,%6,%7},{%8,%9},{%0,%1,%2,%3};"
        : "+f"(d[0]), "+f"(d[1]), "+f"(d[2]), "+f"(d[3])
        : "r"(a[0]), "r"(a[1]), "r"(a[2]), "r"(a[3]), "r"(b[0]), "r"(b[1]));
}
__device__ __forceinline__ void split1(float x, u16& hi, u16& lo) {
    __nv_bfloat16 h = __float2bfloat16(x);
    __nv_bfloat16 l = __float2bfloat16(x - __bfloat162float(h));
    hi = *(u16*)&h;  lo = *(u16*)&l;
}
__device__ __forceinline__ void split1h(float x, u16& hi, u16& lo) {
    __half h = __float2half_rn(x);
    __half l = __float2half_rn(x - __half2float(h));
    hi = *(u16*)&h;  lo = *(u16*)&l;
}
__device__ __forceinline__ void split2h(float x0, float x1, u32& hi, u32& lo) {
    __half2 h = __floats2half2_rn(x0, x1);
    float r0 = x0 - __half2float(__low2half(h));
    float r1 = x1 - __half2float(__high2half(h));
    __half2 l = __floats2half2_rn(r0, r1);
    hi = *(u32*)&h;  lo = *(u32*)&l;
}
__device__ __forceinline__ u32 pack_h2(float x0, float x1) {
    __half2 h = __floats2half2_rn(x0, x1);
    return *(u32*)&h;
}
__device__ __forceinline__ void cpasync16(u32 dst, const void* src) {
    asm volatile("cp.async.cg.shared.global [%0], [%1], 16;" :: "r"(dst), "l"(src));
}

// ---------- kernel 0: fused W + Wo prep (fp16 splits) ----------
__global__ void prep_kernel(const float* __restrict__ Wq,
                            const float* __restrict__ Wk,
                            const float* __restrict__ Wv,
                            const float* __restrict__ Wo) {
    int idx = blockIdx.x*256 + threadIdx.x;
    if (idx < 196608) {
        int kk = idx & 31;
        int r  = idx >> 5;
        int n  = r % 192;
        int it = r / 192;
        int col = n & 63;
        const float* Wp = (n < 64) ? Wq : (n < 128) ? Wk : Wv;
        float w = Wp[(size_t)(it*32 + kk)*M_ + col];
        u16 hi, lo;
        split1h(w, hi, lo);
        g_Wh[idx] = hi;
        g_Wl[idx] = lo;
    } else {
        int i2 = idx - 196608;
        int kp = i2 & 31;
        int n  = (i2 >> 5) & 127;
        int blk = i2 >> 12;
        int ng = blk*128 + n;
        u32 hi, lo;
        split2h(Wo[(size_t)(2*kp)*D_ + ng], Wo[(size_t)(2*kp+1)*D_ + ng], hi, lo);
        g_WoH[i2] = hi;
        g_WoL[i2] = lo;
    }
}

// SMEM layout for qkv
#define RS 80
#define CRS 144
#define XHo(b)  ((b)*5120)
#define WHo(b)  (10240 + (b)*15360)
#define WLo(b)  (40960 + (b)*15360)
#define FS_AH 0
#define FS_AL 9216
#define FS_BH 18432
#define FS_BL 27648
#define WGV_OFF 71680
#define GATE_OFF 75776
#define DPOW_OFF 76032
#define QKV_SMEM 76288

// ========== kernel 1: fused QKV + gate + chunk-sum (A^T), 2 CTAs/SM ========
__global__ void __launch_bounds__(256, 2) qkv_mma_kernel(
        const float* __restrict__ x,
        const float* __restrict__ Wg, const float* __restrict__ bg,
        const float* __restrict__ dp) {
    extern __shared__ char smem[];
    u32 sb = smem_u32(smem);
    int t = threadIdx.x;
    int lane = t & 31, wid = t >> 5;
    int warp_m = wid >> 2, warp_n = wid & 3;
    int r0 = blockIdx.x * 64;

    *(float4*)(smem + WGV_OFF + t*16) = *(const float4*)(Wg + t*4);
    const float* wgs = (const float*)(smem + WGV_OFF);
    float* dpow = (float*)(smem + DPOW_OFF);
    if (t < 64) dpow[t] = powf(decay_val(dp), (float)t);

    int rowX = t >> 3;
    int c4   = t & 7;

    int wn[6], wc[6], wterm[6];
#pragma unroll
    for (int rr = 0; rr < 6; ++rr) {
        int idx = t + rr*256;
        wterm[rr] = (idx >= 768);
        int rem = idx - wterm[rr]*768;
        wn[rr] = rem >> 2;
        wc[rr] = rem & 3;
    }

    int laneA_row = lane & 15;
    int laneA_kb  = (lane >> 4) * 16;
    int laneB_n   = (lane & 7) + ((lane >> 4) << 3);
    int laneB_kb  = ((lane >> 3) & 1) * 16;

    float acc[2][6][4];
#pragma unroll
    for (int i = 0; i < 2; ++i)
#pragma unroll
        for (int j = 0; j < 6; ++j)
#pragma unroll
            for (int k = 0; k < 4; ++k) acc[i][j][k] = 0.f;
    float gacc[2] = {0.f, 0.f};

    __syncthreads();

    float4 xr0 = __ldcs((const float4*)(x + (size_t)(r0 + rowX)*D_ + c4*4));
    float4 xr1 = __ldcs((const float4*)(x + (size_t)(r0 + rowX + 32)*D_ + c4*4));
#pragma unroll
    for (int rr = 0; rr < 6; ++rr) {
        u32 dst = sb + (wterm[rr] ? WLo(0) : WHo(0)) + wn[rr]*RS + wc[rr]*16;
        const u16* src = (wterm[rr] ? g_Wl : g_Wh) + ((0*192 + wn[rr])*32 + wc[rr]*8);
        cpasync16(dst, src);
    }
    asm volatile("cp.async.commit_group;" ::: "memory");

#pragma unroll 1
    for (int it = 0; it < 32; ++it) {
        int buf = it & 1;
        int k0 = it * 32;
        {
            const float* wg4 = wgs + k0 + c4*4;
            gacc[0] += xr0.x*wg4[0] + xr0.y*wg4[1] + xr0.z*wg4[2] + xr0.w*wg4[3];
            gacc[1] += xr1.x*wg4[0] + xr1.y*wg4[1] + xr1.z*wg4[2] + xr1.w*wg4[3];
            u32 a0 = pack_h2(xr0.x, xr0.y), a1 = pack_h2(xr0.z, xr0.w);
            *(u64*)(smem + XHo(buf) + rowX*RS + c4*8) = ((u64)a1 << 32) | a0;
            a0 = pack_h2(xr1.x, xr1.y);  a1 = pack_h2(xr1.z, xr1.w);
            *(u64*)(smem + XHo(buf) + (rowX+32)*RS + c4*8) = ((u64)a1 << 32) | a0;
        }
        asm volatile("cp.async.wait_group 0;" ::: "memory");
        __syncthreads();
        if (it < 31) {
            int k1 = k0 + 32;
            xr0 = __ldcs((const float4*)(x + (size_t)(r0 + rowX)*D_ + k1 + c4*4));
            xr1 = __ldcs((const float4*)(x + (size_t)(r0 + rowX + 32)*D_ + k1 + c4*4));
#pragma unroll
            for (int rr = 0; rr < 6; ++rr) {
                u32 dst = sb + (wterm[rr] ? WLo(buf^1) : WHo(buf^1)) + wn[rr]*RS + wc[rr]*16;
                const u16* src = (wterm[rr] ? g_Wl : g_Wh)
                               + (((it+1)*192 + wn[rr])*32 + wc[rr]*8);
                cpasync16(dst, src);
            }
            asm volatile("cp.async.commit_group;" ::: "memory");
        }
#pragma unroll
        for (int ko = 0; ko < 2; ++ko) {
            int kb = ko*32;
            u32 Ah[2][4], Bb[6][2];
#pragma unroll
            for (int mt = 0; mt < 2; ++mt) {
                u32 aoff = (u32)((warp_m*32 + mt*16 + laneA_row)*RS + kb + laneA_kb);
                ldsm4(Ah[mt][0], Ah[mt][1], Ah[mt][2], Ah[mt][3], sb + XHo(buf) + aoff);
            }
#pragma unroll
            for (int np = 0; np < 3; ++np) {
                u32 boff = (u32)((warp_n*48 + np*16 + laneB_n)*RS + kb + laneB_kb);
                ldsm4(Bb[2*np][0], Bb[2*np][1], Bb[2*np+1][0], Bb[2*np+1][1],
                      sb + WHo(buf) + boff);
            }
#pragma unroll
            for (int mt = 0; mt < 2; ++mt)
#pragma unroll
                for (int nt = 0; nt < 6; ++nt) mma_f16(acc[mt][nt], Ah[mt], Bb[nt]);
#pragma unroll
            for (int np = 0; np < 3; ++np) {
                u32 boff = (u32)((warp_n*48 + np*16 + laneB_n)*RS + kb + laneB_kb);
                ldsm4(Bb[2*np][0], Bb[2*np][1], Bb[2*np+1][0], Bb[2*np+1][1],
                      sb + WLo(buf) + boff);
            }
#pragma unroll
            for (int mt = 0; mt < 2; ++mt)
#pragma unroll
                for (int nt = 0; nt < 6; ++nt) mma_f16(acc[mt][nt], Ah[mt], Bb[nt]);
        }
    }

    // ---- gates ----
#pragma unroll
    for (int off = 4; off; off >>= 1)
#pragma unroll
        for (int rep = 0; rep < 2; ++rep)
            gacc[rep] += __shfl_xor_sync(0xffffffffu, gacc[rep], off);
    if ((t & 7) == 0) {
        float bgv = bg[0];
        ((float*)(smem + GATE_OFF))[rowX]      = 1.0f/(1.0f + expf(-(gacc[0] + bgv)));
        ((float*)(smem + GATE_OFF))[rowX + 32] = 1.0f/(1.0f + expf(-(gacc[1] + bgv)));
    }
    __syncthreads();
    const float* gate = (const float*)(smem + GATE_OFF);

    // ---- epilogue: fp16 global writes + fused chunk-sum staging ----
    int g8 = lane >> 2, t2 = lane & 3;
#pragma unroll
    for (int mt = 0; mt < 2; ++mt) {
        int rl0 = warp_m*32 + mt*16 + g8;
        float w0 = dpow[63 - rl0], w1 = dpow[63 - (rl0 + 8)];
#pragma unroll
        for (int nt = 0; nt < 6; ++nt) {
            int col = warp_n*48 + nt*8 + t2*2;
            int proj = col >> 6, pair = (col & 63) >> 1;
            int lc = col & 63;
            float ga = (proj == 0) ? 1.0f : gate[rl0];
            float gb = (proj == 0) ? 1.0f : gate[rl0 + 8];
            float v0 = acc[mt][nt][0]*ga, v1 = acc[mt][nt][1]*ga;
            float v2 = acc[mt][nt][2]*gb, v3 = acc[mt][nt][3]*gb;
            if (proj == 0) {
                g_Qf[(size_t)(r0 + rl0)*32 + pair]     = pack_h2(v0, v1);
                g_Qf[(size_t)(r0 + rl0 + 8)*32 + pair] = pack_h2(v2, v3);
            } else {
                u32* OutH = (proj == 1) ? g_KH : g_VH;
                u32* OutL = (proj == 1) ? g_KL : g_VL;
                u32 hi, lo;
                split2h(v0, v1, hi, lo);
                OutH[(size_t)(r0 + rl0)*32 + pair] = hi;
                OutL[(size_t)(r0 + rl0)*32 + pair] = lo;
                split2h(v2, v3, hi, lo);
                OutH[(size_t)(r0 + rl0 + 8)*32 + pair] = hi;
                OutL[(size_t)(r0 + rl0 + 8)*32 + pair] = lo;
            }
            if (proj == 1) {        // GKw^T -> B operand (bf16 split, decay-weighted)
                u16 h16, l16;
                split1(v0*w0, h16, l16);
                *(u16*)(smem + FS_BH + lc*CRS + rl0*2) = h16;
                *(u16*)(smem + FS_BL + lc*CRS + rl0*2) = l16;
                split1(v1*w0, h16, l16);
                *(u16*)(smem + FS_BH + (lc+1)*CRS + rl0*2) = h16;
                *(u16*)(smem + FS_BL + (lc+1)*CRS + rl0*2) = l16;
                split1(v2*w1, h16, l16);
                *(u16*)(smem + FS_BH + lc*CRS + (rl0+8)*2) = h16;
                *(u16*)(smem + FS_BL + lc*CRS + (rl0+8)*2) = l16;
                split1(v3*w1, h16, l16);
                *(u16*)(smem + FS_BH + (lc+1)*CRS + (rl0+8)*2) = h16;
                *(u16*)(smem + FS_BL + (lc+1)*CRS + (rl0+8)*2) = l16;
            } else if (proj == 2) { // GV^T -> A operand (bf16 split)
                u16 h16, l16;
                split1(v0, h16, l16);
                *(u16*)(smem + FS_AH + lc*CRS + rl0*2) = h16;
                *(u16*)(smem + FS_AL + lc*CRS + rl0*2) = l16;
                split1(v1, h16, l16);
                *(u16*)(smem + FS_AH + (lc+1)*CRS + rl0*2) = h16;
                *(u16*)(smem + FS_AL + (lc+1)*CRS + rl0*2) = l16;
                split1(v2, h16, l16);
                *(u16*)(smem + FS_AH + lc*CRS + (rl0+8)*2) = h16;
                *(u16*)(smem + FS_AL + lc*CRS + (rl0+8)*2) = l16;
                split1(v3, h16, l16);
                *(u16*)(smem + FS_AH + (lc+1)*CRS + (rl0+8)*2) = h16;
                *(u16*)(smem + FS_AL + (lc+1)*CRS + (rl0+8)*2) = l16;
            }
        }
    }
    __syncthreads();

    // ---- fused chunk-sum MMA: A^T = GV^T @ GKw (bf16 3-term) ----
    {
        int cwm = wid >> 1, cwn = wid & 1;
        float cacc[4][4];
#pragma unroll
        for (int j = 0; j < 4; ++j)
#pragma unroll
            for (int k = 0; k < 4; ++k) cacc[j][k] = 0.f;
#pragma unroll
        for (int ko = 0; ko < 4; ++ko) {
            int kb = ko*32;
            u32 Ah[4], Al[4], Bb[4][2];
            u32 aoff = (u32)((cwm*16 + laneA_row)*CRS + kb + laneA_kb);
            ldsm4(Ah[0], Ah[1], Ah[2], Ah[3], sb + FS_AH + aoff);
            ldsm4(Al[0], Al[1], Al[2], Al[3], sb + FS_AL + aoff);
#pragma unroll
            for (int np = 0; np < 2; ++np) {
                u32 boff = (u32)((cwn*32 + np*16 + laneB_n)*CRS + kb + laneB_kb);
                ldsm4(Bb[2*np][0], Bb[2*np][1], Bb[2*np+1][0], Bb[2*np+1][1],
                      sb + FS_BH + boff);
            }
#pragma unroll
            for (int nt = 0; nt < 4; ++nt) mma_bf16(cacc[nt], Ah, Bb[nt]);
#pragma unroll
            for (int nt = 0; nt < 4; ++nt) mma_bf16(cacc[nt], Al, Bb[nt]);
#pragma unroll
            for (int np = 0; np < 2; ++np) {
                u32 boff = (u32)((cwn*32 + np*16 + laneB_n)*CRS + kb + laneB_kb);
                ldsm4(Bb[2*np][0], Bb[2*np][1], Bb[2*np+1][0], Bb[2*np+1][1],
                      sb + FS_BL + boff);
            }
#pragma unroll
            for (int nt = 0; nt < 4; ++nt) mma_bf16(cacc[nt], Ah, Bb[nt]);
        }
        size_t ab = (size_t)blockIdx.x * (M_*M_);
#pragma unroll
        for (int nt = 0; nt < 4; ++nt) {
            int j = cwn*32 + nt*8 + t2*2;
            int i0 = cwm*16 + g8;
            *(float2*)(g_A + ab + (size_t)i0*M_ + j)     = make_float2(cacc[nt][0], cacc[nt][1]);
            *(float2*)(g_A + ab + (size_t)(i0+8)*M_ + j) = make_float2(cacc[nt][2], cacc[nt][3]);
        }
    }
}

// --------- kernel 4: inter-chunk scan (float2/thread, MLP-8) ----------
__global__ void chunk_scan_kernel(const float* __restrict__ dp,
                                  float* __restrict__ sfinal) {
    int gid = blockIdx.x * blockDim.x + threadIdx.x;
    int b = gid >> 11;
    int e = (gid & 2047) * 2;
    float d  = decay_val(dp);
    float dT = powf(d, 64.0f);
    float2 S = make_float2(0.f, 0.f);
#pragma unroll 1
    for (int c0 = 0; c0 < C_; c0 += 8) {
        float2 a[8];
#pragma unroll
        for (int j = 0; j < 8; ++j)
            a[j] = *(const float2*)(g_A + ((size_t)(b*C_ + c0 + j) << 12) + e);
#pragma unroll
        for (int j = 0; j < 8; ++j) {
            *(float2*)(g_Spre + ((size_t)(b*C_ + c0 + j) << 12) + e) = S;
            S.x = dT*S.x + a[j].x;
            S.y = dT*S.y + a[j].y;
        }
    }
    __stcs(sfinal + ((size_t)b << 12) + (e & 63)*64 + (e >> 6), S.x);
    __stcs(sfinal + ((size_t)b << 12) + ((e+1) & 63)*64 + ((e+1) >> 6), S.y);
}

// --------- kernel 5: per-chunk outputs (fp16 2-term) -----------------------
#define CO_Q  0
#define CO_P  9216
#define CO_BH 18432
#define CO_BL 27648
#define CO_DP 36864
#define CO_SMEM 37376

__global__ void __launch_bounds__(256) chunk_out_kernel(const float* __restrict__ dp) {
    extern __shared__ char smem[];
    u32 sb = smem_u32(smem);
    int b = blockIdx.y, c = blockIdx.x;
    int t = threadIdx.x, lane = t & 31, wid = t >> 5;
    int warp_m = wid >> 1, warp_n = wid & 1;
    float d = decay_val(dp);
    float* dpow = (float*)(smem + CO_DP);
    if (t < 65) dpow[t] = powf(d, (float)t);

    size_t grow = (size_t)b*L_ + (size_t)c*T_;
    size_t sbase = (size_t)(b*C_ + c) * (M_*M_);

    // stage Q (single fp16, A natural) + Kh/Kl (B natural) via cp.async
#pragma unroll
    for (int rep = 0; rep < 2; ++rep) {
        int idx = t + rep*256;
        int row = idx >> 3, ch = idx & 7;
        u32 off = row*CRS + ch*16;
        cpasync16(sb + CO_Q  + off, g_Qf + (grow + row)*32 + ch*4);
        cpasync16(sb + CO_BH + off, g_KH + (grow + row)*32 + ch*4);
        cpasync16(sb + CO_BL + off, g_KL + (grow + row)*32 + ch*4);
    }
    asm volatile("cp.async.commit_group;" ::: "memory");
    asm volatile("cp.async.wait_group 0;" ::: "memory");
    __syncthreads();

    int laneA_row = lane & 15;
    int laneA_kb  = (lane >> 4) * 16;
    int laneB_n   = (lane & 7) + ((lane >> 4) << 3);
    int laneB_kb  = ((lane >> 3) & 1) * 16;
    int g8 = lane >> 2, t2 = lane & 3;

    // phase 1: P = Q @ GK^T (fp16 2-term)
    float pacc[4][4];
#pragma unroll
    for (int j = 0; j < 4; ++j)
#pragma unroll
        for (int k = 0; k < 4; ++k) pacc[j][k] = 0.f;
#pragma unroll
    for (int ko = 0; ko < 4; ++ko) {
        int kb = ko*32;
        u32 Aq[4], Bb[4][2];
        u32 aoff = (u32)((warp_m*16 + laneA_row)*CRS + kb + laneA_kb);
        ldsm4(Aq[0], Aq[1], Aq[2], Aq[3], sb + CO_Q + aoff);
#pragma unroll
        for (int np = 0; np < 2; ++np) {
            u32 boff = (u32)((warp_n*32 + np*16 + laneB_n)*CRS + kb + laneB_kb);
            ldsm4(Bb[2*np][0], Bb[2*np][1], Bb[2*np+1][0], Bb[2*np+1][1],
                  sb + CO_BH + boff);
        }
#pragma unroll
        for (int nt = 0; nt < 4; ++nt) mma_f16(pacc[nt], Aq, Bb[nt]);
#pragma unroll
        for (int np = 0; np < 2; ++np) {
            u32 boff = (u32)((warp_n*32 + np*16 + laneB_n)*CRS + kb + laneB_kb);
            ldsm4(Bb[2*np][0], Bb[2*np][1], Bb[2*np+1][0], Bb[2*np+1][1],
                  sb + CO_BL + boff);
        }
#pragma unroll
        for (int nt = 0; nt < 4; ++nt) mma_f16(pacc[nt], Aq, Bb[nt]);
    }
    // mask + decay -> P single fp16
#pragma unroll
    for (int nt = 0; nt < 4; ++nt) {
        int colb = warp_n*32 + nt*8 + t2*2;
        int ra = warp_m*16 + g8;
        float p0 = (colb   <= ra) ? pacc[nt][0]*dpow[ra - colb]     : 0.f;
        float p1 = (colb+1 <= ra) ? pacc[nt][1]*dpow[ra - colb - 1] : 0.f;
        int rb = ra + 8;
        float p2 = (colb   <= rb) ? pacc[nt][2]*dpow[rb - colb]     : 0.f;
        float p3 = (colb+1 <= rb) ? pacc[nt][3]*dpow[rb - colb - 1] : 0.f;
        *(u32*)(smem + CO_P + ra*CRS + colb*2) = pack_h2(p0, p1);
        *(u32*)(smem + CO_P + rb*CRS + colb*2) = pack_h2(p2, p3);
    }
    __syncthreads();

    // stage Spre^T split fp16
#pragma unroll
    for (int rep = 0; rep < 4; ++rep) {
        int idx = t + rep*256;
        int row = idx >> 4, c4 = idx & 15;
        float4 v = *(const float4*)(g_Spre + sbase + (size_t)row*M_ + c4*4);
        u32 h0,l0,h1,l1;
        split2h(v.x, v.y, h0, l0);
        split2h(v.z, v.w, h1, l1);
        int off = row*CRS + c4*8;
        *(u32*)(smem + CO_BH + off)   = h0;
        *(u32*)(smem + CO_BH + off+4) = h1;
        *(u32*)(smem + CO_BL + off)   = l0;
        *(u32*)(smem + CO_BL + off+4) = l1;
    }
    __syncthreads();

    // phase 2: acc = Q @ Spre (fp16 2-term)
    float acc[4][4];
#pragma unroll
    for (int j = 0; j < 4; ++j)
#pragma unroll
        for (int k = 0; k < 4; ++k) acc[j][k] = 0.f;
#pragma unroll
    for (int ko = 0; ko < 4; ++ko) {
        int kb = ko*32;
        u32 Aq[4], Bb[4][2];
        u32 aoff = (u32)((warp_m*16 + laneA_row)*CRS + kb + laneA_kb);
        ldsm4(Aq[0], Aq[1], Aq[2], Aq[3], sb + CO_Q + aoff);
#pragma unroll
        for (int np = 0; np < 2; ++np) {
            u32 boff = (u32)((warp_n*32 + np*16 + laneB_n)*CRS + kb + laneB_kb);
            ldsm4(Bb[2*np][0], Bb[2*np][1], Bb[2*np+1][0], Bb[2*np+1][1],
                  sb + CO_BH + boff);
        }
#pragma unroll
        for (int nt = 0; nt < 4; ++nt) mma_f16(acc[nt], Aq, Bb[nt]);
#pragma unroll
        for (int np = 0; np < 2; ++np) {
            u32 boff = (u32)((warp_n*32 + np*16 + laneB_n)*CRS + kb + laneB_kb);
            ldsm4(Bb[2*np][0], Bb[2*np][1], Bb[2*np+1][0], Bb[2*np+1][1],
                  sb + CO_BL + boff);
        }
#pragma unroll
        for (int nt = 0; nt < 4; ++nt) mma_f16(acc[nt], Aq, Bb[nt]);
    }
    {
        int ra = warp_m*16 + g8;
        float sa = dpow[ra + 1], sbc = dpow[ra + 9];
#pragma unroll
        for (int nt = 0; nt < 4; ++nt) {
            acc[nt][0] *= sa;  acc[nt][1] *= sa;
            acc[nt][2] *= sbc; acc[nt][3] *= sbc;
        }
    }
    __syncthreads();

    // stage GV^T from fp16 split pairs
#pragma unroll
    for (int rep = 0; rep < 8; ++rep) {
        int idx = t + rep*256;
        int s = idx >> 5, p = idx & 31;
        u32 vh = g_VH[(grow+s)*32 + p], vl = g_VL[(grow+s)*32 + p];
        *(u16*)(smem + CO_BH + (2*p)*CRS   + s*2) = (u16)(vh & 0xffff);
        *(u16*)(smem + CO_BH + (2*p+1)*CRS + s*2) = (u16)(vh >> 16);
        *(u16*)(smem + CO_BL + (2*p)*CRS   + s*2) = (u16)(vl & 0xffff);
        *(u16*)(smem + CO_BL + (2*p+1)*CRS + s*2) = (u16)(vl >> 16);
    }
    __syncthreads();

    // phase 3: acc += P @ GV (fp16 2-term, P single)
#pragma unroll
    for (int ko = 0; ko < 4; ++ko) {
        int kb = ko*32;
        u32 Ap[4], Bb[4][2];
        u32 aoff = (u32)((warp_m*16 + laneA_row)*CRS + kb + laneA_kb);
        ldsm4(Ap[0], Ap[1], Ap[2], Ap[3], sb + CO_P + aoff);
#pragma unroll
        for (int np = 0; np < 2; ++np) {
            u32 boff = (u32)((warp_n*32 + np*16 + laneB_n)*CRS + kb + laneB_kb);
            ldsm4(Bb[2*np][0], Bb[2*np][1], Bb[2*np+1][0], Bb[2*np+1][1],
                  sb + CO_BH + boff);
        }
#pragma unroll
        for (int nt = 0; nt < 4; ++nt) mma_f16(acc[nt], Ap, Bb[nt]);
#pragma unroll
        for (int np = 0; np < 2; ++np) {
            u32 boff = (u32)((warp_n*32 + np*16 + laneB_n)*CRS + kb + laneB_kb);
            ldsm4(Bb[2*np][0], Bb[2*np][1], Bb[2*np+1][0], Bb[2*np+1][1],
                  sb + CO_BL + boff);
        }
#pragma unroll
        for (int nt = 0; nt < 4; ++nt) mma_f16(acc[nt], Ap, Bb[nt]);
    }

    // write O fp16 pairs
#pragma unroll
    for (int nt = 0; nt < 4; ++nt) {
        int j = warp_n*32 + nt*8 + t2*2;
        int pair = j >> 1;
        int i0 = warp_m*16 + g8;
        g_OHf[(grow + i0)*32 + pair]     = pack_h2(acc[nt][0], acc[nt][1]);
        g_OHf[(grow + i0 + 8)*32 + pair] = pack_h2(acc[nt][2], acc[nt][3]);
    }
}

// ---------- kernel 6: y = O @ Wo + bo (fp16 2-term; streaming y) ----------
#define OH_OFF 0
#define WHO_OFF 18432
#define WLO_OFF 36864
#define OUT_SMEM 55296
#define ORS 144

__global__ void __launch_bounds__(256, 2) out_mma_kernel(
        const float* __restrict__ bo, float* __restrict__ y) {
    extern __shared__ char smem[];
    u32 sb = smem_u32(smem);
    int t = threadIdx.x;
    int lane = t & 31, wid = t >> 5;
    int warp_m = wid >> 1, warp_n = wid & 1;
    int r0 = blockIdx.x * 128;
    int n0 = blockIdx.y * 128;
    int blk = blockIdx.y;

#pragma unroll
    for (int p = 0; p < 4; ++p) {
        int idx = t + p*256;
        int row = idx >> 3, ch = idx & 7;
        cpasync16(sb + WHO_OFF + row*ORS + ch*16, g_WoH + ((blk*128 + row)*32 + ch*4));
        cpasync16(sb + WLO_OFF + row*ORS + ch*16, g_WoL + ((blk*128 + row)*32 + ch*4));
        cpasync16(sb + OH_OFF + row*ORS + ch*16, g_OHf + ((size_t)(r0 + row)*32 + ch*4));
    }
    asm volatile("cp.async.commit_group;" ::: "memory");
    asm volatile("cp.async.wait_group 0;" ::: "memory");
    __syncthreads();

    int laneA_row = lane & 15;
    int laneA_kb  = (lane >> 4) * 16;
    int laneB_n   = (lane & 7) + ((lane >> 4) << 3);
    int laneB_kb  = ((lane >> 3) & 1) * 16;

    float acc[2][8][4];
#pragma unroll
    for (int i = 0; i < 2; ++i)
#pragma unroll
        for (int j = 0; j < 8; ++j)
#pragma unroll
            for (int k = 0; k < 4; ++k) acc[i][j][k] = 0.f;

#pragma unroll
    for (int ko = 0; ko < 4; ++ko) {
        int kb = ko*32;
        u32 Ah[2][4], Bb[8][2];
#pragma unroll
        for (int mt = 0; mt < 2; ++mt) {
            u32 aoff = (u32)((warp_m*32 + mt*16 + laneA_row)*ORS + kb + laneA_kb);
            ldsm4(Ah[mt][0], Ah[mt][1], Ah[mt][2], Ah[mt][3], sb + OH_OFF + aoff);
        }
#pragma unroll
        for (int np = 0; np < 4; ++np) {
            u32 boff = (u32)((warp_n*64 + np*16 + laneB_n)*ORS + kb + laneB_kb);
            ldsm4(Bb[2*np][0], Bb[2*np][1], Bb[2*np+1][0], Bb[2*np+1][1],
                  sb + WHO_OFF + boff);
        }
#pragma unroll
        for (int mt = 0; mt < 2; ++mt)
#pragma unroll
            for (int nt = 0; nt < 8; ++nt) mma_f16(acc[mt][nt], Ah[mt], Bb[nt]);
#pragma unroll
        for (int np = 0; np < 4; ++np) {
            u32 boff = (u32)((warp_n*64 + np*16 + laneB_n)*ORS + kb + laneB_kb);
            ldsm4(Bb[2*np][0], Bb[2*np][1], Bb[2*np+1][0], Bb[2*np+1][1],
                  sb + WLO_OFF + boff);
        }
#pragma unroll
        for (int mt = 0; mt < 2; ++mt)
#pragma unroll
            for (int nt = 0; nt < 8; ++nt) mma_f16(acc[mt][nt], Ah[mt], Bb[nt]);
    }

    int g8 = lane >> 2, t2 = lane & 3;
#pragma unroll
    for (int mt = 0; mt < 2; ++mt) {
        int row = r0 + warp_m*32 + mt*16 + g8;
#pragma unroll
        for (int nt = 0; nt < 8; ++nt) {
            int col = n0 + warp_n*64 + nt*8 + t2*2;
            float2 bias = *(const float2*)(bo + col);
            __stcs((float2*)(y + (size_t)row*D_ + col),
                   make_float2(acc[mt][nt][0] + bias.x, acc[mt][nt][1] + bias.y));
            __stcs((float2*)(y + (size_t)(row + 8)*D_ + col),
                   make_float2(acc[mt][nt][2] + bias.x, acc[mt][nt][3] + bias.y));
        }
    }
}

// ---------------- launcher ----------------
extern "C" void kernel_launch(void* const* d_in, const int* in_sizes, int n_in,
                              void* d_out, int out_size) {
    const float* x  = (const float*)d_in[0];
    const float* Wq = (const float*)d_in[1];
    const float* Wk = (const float*)d_in[2];
    const float* Wv = (const float*)d_in[3];
    const float* Wo = (const float*)d_in[4];
    const float* bo = (const float*)d_in[5];
    const float* Wg = (const float*)d_in[6];
    const float* bg = (const float*)d_in[7];
    const float* dp = (const float*)d_in[8];
    float* y      = (float*)d_out;
    float* sfinal = y + (size_t)BL_ * D_;

    cudaFuncSetAttribute(qkv_mma_kernel,
                         cudaFuncAttributeMaxDynamicSharedMemorySize, QKV_SMEM);
    cudaFuncSetAttribute(out_mma_kernel,
                         cudaFuncAttributeMaxDynamicSharedMemorySize, OUT_SMEM);
    cudaFuncSetAttribute(chunk_out_kernel,
                         cudaFuncAttributeMaxDynamicSharedMemorySize, CO_SMEM);

    prep_kernel      <<<896, 256>>>(Wq, Wk, Wv, Wo);
    qkv_mma_kernel   <<<BL_/64, 256, QKV_SMEM>>>(x, Wg, bg, dp);
    chunk_scan_kernel<<<(B_*M_*M_)/512, 256>>>(dp, sfinal);
    chunk_out_kernel <<<dim3(C_, B_), 256, CO_SMEM>>>(dp);
    out_mma_kernel   <<<dim3(BL_/128, D_/128), 256, OUT_SMEM>>>(bo, y);
}